// round 12
// baseline (speedup 1.0000x reference)
#include <cuda_runtime.h>
#include <math.h>
#include <stdint.h>

#define Bb 8
#define Cc 384
#define Nn 1024
#define HEADS 8
#define KD 32
#define VD 128
#define QKV_C 1536
#define FC1_C 768
#define EPS 1e-5f

// ---------------- scratch (static device globals; no allocation) ----------------
__device__ float g_y[(long)Bb*QKV_C*Nn];
__device__ float g_vt[(long)Bb*HEADS*Nn*VD];
__device__ float g_o2[(long)Bb*HEADS*VD*Nn];   // gelu(attn out), channel-major [b][ch][n]
__device__ float g_x2[(long)Bb*Cc*Nn];
__device__ float g_h1[(long)Bb*FC1_C*Nn];
__device__ float g_tmp[(long)Bb*FC1_C*Nn];
__device__ float g_mean[QKV_C];
__device__ float g_rstd[QKV_C];
__device__ float g_csum[QKV_C];    // zero-initialized; finalize re-zeroes
__device__ float g_csum2[QKV_C];

__device__ __forceinline__ float gelu_exact(float x){
    return 0.5f * x * (1.0f + erff(x * 0.7071067811865476f));
}
__device__ __forceinline__ float to_tf32(float x){
    uint32_t u;
    asm("cvt.rna.tf32.f32 %0, %1;" : "=r"(u) : "f"(x));
    return __uint_as_float(u);
}
__device__ __forceinline__ float ex2_approx(float x){
    float y;
    asm("ex2.approx.ftz.f32 %0, %1;" : "=f"(y) : "f"(x));
    return y;
}
__device__ __forceinline__ void mma_tf32(float c[4],
    uint32_t a0, uint32_t a1, uint32_t a2, uint32_t a3, uint32_t b0, uint32_t b1)
{
    asm volatile("mma.sync.aligned.m16n8k8.row.col.f32.tf32.tf32.f32 "
        "{%0,%1,%2,%3}, {%4,%5,%6,%7}, {%8,%9}, {%0,%1,%2,%3};"
        : "+f"(c[0]), "+f"(c[1]), "+f"(c[2]), "+f"(c[3])
        : "r"(a0), "r"(a1), "r"(a2), "r"(a3), "r"(b0), "r"(b1));
}
#define U(f) __float_as_uint(f)

// =====================================================================
// tf32 GEMM v3: A[M,K] row-major, B[K,N] k-major (all call sites).
//  - As: scalar layout [k][m], stride 136 (proven conflict-free both ways)
//  - Bs: permuted fragment layout (flash-verified): element (k,n) at
//        k*132 + 16*(n&7) + (n>>3); B-frag loads are LDS.128, stores use
//        the sig lane-remap (<=2-way, measured OK in flash R8).
//  BNB=1: BN(channel=k)+gelu applied to B at global load (fc2<-fc1 raw)
//  STATS=1: per-M-row channel sums via epilogue shuffle+atomics
// =====================================================================
template<int BNB,int STATS>
__global__ __launch_bounds__(256,2) void mm_tf32(
    const float* __restrict__ A, const float* __restrict__ B, float* __restrict__ C,
    int M, int N, int K, int lda, int ldb,
    long strideB, long strideC,
    const float* __restrict__ bnM, const float* __restrict__ bnR,
    const float* __restrict__ bnG, const float* __restrict__ bnBv,
    float* __restrict__ gS, float* __restrict__ gS2)
{
    __shared__ __align__(16) float As[2][16][136];
    __shared__ __align__(16) float Bs[2][16*132];

    const int z = blockIdx.z;
    const float* Ab = A;
    const float* Bc = B + (long)z * strideB;
    float* Cz = C + (long)z * strideC;

    const int bm = blockIdx.y * 128, bn = blockIdx.x * 128;
    const int tid = threadIdx.x;
    const int w = tid >> 5, l = tid & 31;
    const int wm = (w >> 1) * 32, wn = (w & 1) * 64;
    const int r = l >> 2, qc = l & 3;

    // B loader lane mapping (sig remap; coalesced within warp)
    const int sig = ((l & 15) << 1) | (l >> 4);
    const int nq = sig * 4;
    const int bkk0 = tid >> 5, bkk1 = bkk0 + 8;
    // A loader mapping (unchanged)
    const int arow = tid >> 2, akq = (tid & 3) * 4;

    float acc[2][8][4];
    #pragma unroll
    for (int i = 0; i < 2; i++)
        #pragma unroll
        for (int j = 0; j < 8; j++)
            #pragma unroll
            for (int k = 0; k < 4; k++) acc[i][j][k] = 0.f;

    float4 ra[2], rb[2];

    auto gload = [&](int k0){
        ra[0] = *reinterpret_cast<const float4*>(&Ab[(long)(bm + arow) * lda + k0 + akq]);
        ra[1] = *reinterpret_cast<const float4*>(&Ab[(long)(bm + arow + 64) * lda + k0 + akq]);
        #pragma unroll
        for (int j = 0; j < 2; j++){
            int kk = (j == 0) ? bkk0 : bkk1;
            rb[j] = *reinterpret_cast<const float4*>(&Bc[(long)(k0 + kk) * ldb + bn + nq]);
            if (BNB) {
                int c = k0 + kk;
                float a = bnR[c]*bnG[c];
                float sh = bnBv[c] - bnM[c]*a;
                rb[j].x = gelu_exact(rb[j].x*a+sh);
                rb[j].y = gelu_exact(rb[j].y*a+sh);
                rb[j].z = gelu_exact(rb[j].z*a+sh);
                rb[j].w = gelu_exact(rb[j].w*a+sh);
            }
        }
    };

    auto sstore = [&](int buf){
        #pragma unroll
        for (int j = 0; j < 2; j++){
            int row = arow + j*64;
            As[buf][akq+0][row] = to_tf32(ra[j].x);
            As[buf][akq+1][row] = to_tf32(ra[j].y);
            As[buf][akq+2][row] = to_tf32(ra[j].z);
            As[buf][akq+3][row] = to_tf32(ra[j].w);
        }
        #pragma unroll
        for (int j = 0; j < 2; j++){
            int kk = (j == 0) ? bkk0 : bkk1;
            int base = kk*132 + (nq & 7)*16 + (nq >> 3);
            Bs[buf][base     ] = to_tf32(rb[j].x);
            Bs[buf][base + 16] = to_tf32(rb[j].y);
            Bs[buf][base + 32] = to_tf32(rb[j].z);
            Bs[buf][base + 48] = to_tf32(rb[j].w);
        }
    };

    auto compute = [&](int buf){
        #pragma unroll
        for (int ks = 0; ks < 16; ks += 8){
            uint32_t af[2][4];
            #pragma unroll
            for (int im = 0; im < 2; im++){
                af[im][0] = U(As[buf][ks+qc  ][wm+im*16+r  ]);
                af[im][1] = U(As[buf][ks+qc  ][wm+im*16+r+8]);
                af[im][2] = U(As[buf][ks+qc+4][wm+im*16+r  ]);
                af[im][3] = U(As[buf][ks+qc+4][wm+im*16+r+8]);
            }
            float4 bL0 = *reinterpret_cast<const float4*>(&Bs[buf][(ks+qc  )*132 + r*16 + (wn>>3)    ]);
            float4 bL1 = *reinterpret_cast<const float4*>(&Bs[buf][(ks+qc  )*132 + r*16 + (wn>>3) + 4]);
            float4 bH0 = *reinterpret_cast<const float4*>(&Bs[buf][(ks+qc+4)*132 + r*16 + (wn>>3)    ]);
            float4 bH1 = *reinterpret_cast<const float4*>(&Bs[buf][(ks+qc+4)*132 + r*16 + (wn>>3) + 4]);
            #pragma unroll
            for (int im = 0; im < 2; im++){
                mma_tf32(acc[im][0], af[im][0],af[im][1],af[im][2],af[im][3], U(bL0.x),U(bH0.x));
                mma_tf32(acc[im][1], af[im][0],af[im][1],af[im][2],af[im][3], U(bL0.y),U(bH0.y));
                mma_tf32(acc[im][2], af[im][0],af[im][1],af[im][2],af[im][3], U(bL0.z),U(bH0.z));
                mma_tf32(acc[im][3], af[im][0],af[im][1],af[im][2],af[im][3], U(bL0.w),U(bH0.w));
                mma_tf32(acc[im][4], af[im][0],af[im][1],af[im][2],af[im][3], U(bL1.x),U(bH1.x));
                mma_tf32(acc[im][5], af[im][0],af[im][1],af[im][2],af[im][3], U(bL1.y),U(bH1.y));
                mma_tf32(acc[im][6], af[im][0],af[im][1],af[im][2],af[im][3], U(bL1.z),U(bH1.z));
                mma_tf32(acc[im][7], af[im][0],af[im][1],af[im][2],af[im][3], U(bL1.w),U(bH1.w));
            }
        }
    };

    gload(0); sstore(0); __syncthreads();
    int buf = 0;
    for (int k0 = 0; k0 < K; k0 += 16){
        bool more = (k0 + 16) < K;
        if (more) gload(k0 + 16);
        compute(buf);
        if (more) { sstore(buf ^ 1); buf ^= 1; }
        __syncthreads();
    }

    #pragma unroll
    for (int im = 0; im < 2; im++){
        float sl = 0.f, s2l = 0.f, shv = 0.f, s2h = 0.f;
        #pragma unroll
        for (int jn = 0; jn < 8; jn++){
            float v0 = acc[im][jn][0], v1 = acc[im][jn][1];
            float v2 = acc[im][jn][2], v3 = acc[im][jn][3];
            int row = bm + wm + im*16 + r;
            int col = bn + wn + jn*8 + 2*qc;
            *reinterpret_cast<float2*>(&Cz[(long)row * N + col])     = make_float2(v0, v1);
            *reinterpret_cast<float2*>(&Cz[(long)(row+8) * N + col]) = make_float2(v2, v3);
            if (STATS) {
                sl  += v0 + v1;       s2l += v0*v0 + v1*v1;
                shv += v2 + v3;       s2h += v2*v2 + v3*v3;
            }
        }
        if (STATS) {
            sl  += __shfl_xor_sync(0xffffffffu, sl, 1);
            sl  += __shfl_xor_sync(0xffffffffu, sl, 2);
            s2l += __shfl_xor_sync(0xffffffffu, s2l, 1);
            s2l += __shfl_xor_sync(0xffffffffu, s2l, 2);
            shv += __shfl_xor_sync(0xffffffffu, shv, 1);
            shv += __shfl_xor_sync(0xffffffffu, shv, 2);
            s2h += __shfl_xor_sync(0xffffffffu, s2h, 1);
            s2h += __shfl_xor_sync(0xffffffffu, s2h, 2);
            if (qc == 0) {
                int row = bm + wm + im*16 + r;
                atomicAdd(&gS[row],    sl);
                atomicAdd(&gS2[row],   s2l);
                atomicAdd(&gS[row+8],  shv);
                atomicAdd(&gS2[row+8], s2h);
            }
        }
    }
}

// ---------------- BN finalize: mean/rstd from sums; re-zero sums ----------------
__global__ void bn_finalize(float* __restrict__ sum, float* __restrict__ sum2,
                            float* __restrict__ mean, float* __restrict__ rstd, int C)
{
    int c = blockIdx.x * blockDim.x + threadIdx.x;
    if (c < C) {
        const float inv = 1.0f / (float)(Bb * Nn);
        float m = sum[c] * inv;
        float v = sum2[c] * inv - m * m;
        mean[c] = m;
        rstd[c] = rsqrtf(v + EPS);
        sum[c] = 0.f;
        sum2[c] = 0.f;
    }
}

// =====================================================================
// V transpose + BN
// =====================================================================
__global__ __launch_bounds__(256) void transpose_v(const float* __restrict__ y,
    float* __restrict__ vt,
    const float* __restrict__ mean, const float* __restrict__ rstd,
    const float* __restrict__ gg, const float* __restrict__ bbias)
{
    __shared__ float t[32][33];
    const int z = blockIdx.z, b = z >> 3, h = z & 7;
    const float* V = y + ((long)b * QKV_C + h * 192 + 64) * Nn;
    const int n0 = blockIdx.x * 32, d0 = blockIdx.y * 32;
    const int tx = threadIdx.x, ty = threadIdx.y;  // 32 x 8
    #pragma unroll
    for (int j = 0; j < 4; j++){
        int d = d0 + ty + j*8;
        int ch = h*192 + 64 + d;
        float a = rstd[ch]*gg[ch];
        float sh = bbias[ch] - mean[ch]*a;
        t[ty + j*8][tx] = V[(long)d * Nn + n0 + tx] * a + sh;
    }
    __syncthreads();
    float* dst = vt + (long)z * Nn * VD;
    #pragma unroll
    for (int j = 0; j < 4; j++)
        dst[(long)(n0 + ty + j*8) * VD + d0 + tx] = to_tf32(t[tx][ty + j*8]);
}

// =====================================================================
// Flash attention — R8 core (measured best 206us), epilogue now writes
// o2 CHANNEL-MAJOR [b][ch][n] so the merge GEMM consumes it k-major.
// =====================================================================
#define FQ  0
#define FK  (4*8*32*4)
#define FV  (FK + 32*132)
#define FP  (FV + 64*132)
#define FCO (FP + 64*136)
#define FLS (FCO + 128)
#define FTOT ((FLS + 128) * 4)

__global__ __launch_bounds__(256,2) void flash_att(
    const float* __restrict__ y, const float* __restrict__ vt,
    float* __restrict__ o2,
    const float* __restrict__ mean, const float* __restrict__ rstd,
    const float* __restrict__ gg, const float* __restrict__ bbias,
    float scale)
{
    extern __shared__ float sm[];
    float* Qp = sm + FQ;
    float* Ks = sm + FK;
    float* Vs = sm + FV;
    float* Ps = sm + FP;
    float* co = sm + FCO;
    float* Ls = sm + FLS;

    const int z = blockIdx.y, b = z >> 3, h = z & 7;
    const float* Q   = y + ((long)b * QKV_C + h * 192) * Nn;
    const float* Kg  = Q + 32 * Nn;
    const float* Vtz = vt + (long)z * Nn * VD;
    const int qt = blockIdx.x * 128;
    const int tid = threadIdx.x, w = tid >> 5, l = tid & 31;
    const int r = l >> 2, qc = l & 3;
    const int wq = w * 16;
    const int g = w >> 1, e = w & 1;
    const int qb = g * 32;

    if (tid < 32) {
        int ch = h*192 + tid;
        float a = rstd[ch]*gg[ch]*scale*1.44269504088896f;
        co[tid]    = a;
        co[32+tid] = (bbias[ch] - mean[ch]*rstd[ch]*gg[ch])*scale*1.44269504088896f;
    } else if (tid < 64) {
        int d = tid - 32;
        int ch = h*192 + 32 + d;
        float a = rstd[ch]*gg[ch];
        co[64+d] = a;
        co[96+d] = bbias[ch] - mean[ch]*a;
    }
    __syncthreads();

    for (int i = tid; i < 32*32; i += 256) {
        int d = i >> 5, c = (i & 31) * 4;
        float a = co[d], sh = co[32+d];
        float4 v = *reinterpret_cast<const float4*>(&Q[(long)d * Nn + qt + c]);
        float vv[4] = { to_tf32(v.x*a+sh), to_tf32(v.y*a+sh),
                        to_tf32(v.z*a+sh), to_tf32(v.w*a+sh) };
        int ksb = d >> 3, dd = d & 7;
        int qcc = dd & 3, jhi = dd >> 2;
        #pragma unroll
        for (int t = 0; t < 4; t++) {
            int q = c + t;
            int ww = q >> 4, qq = q & 15;
            int rr = qq & 7, jlo = qq >> 3;
            Qp[(((ksb*8 + ww)*32) + rr*4 + qcc)*4 + jhi*2 + jlo] = vv[t];
        }
    }

    float oacc[2][8][4];
    #pragma unroll
    for (int im = 0; im < 2; im++)
        #pragma unroll
        for (int j = 0; j < 8; j++)
            oacc[im][j][0] = oacc[im][j][1] = oacc[im][j][2] = oacc[im][j][3] = 0.f;
    float l0 = 0.f, l1 = 0.f;

    for (int kt = 0; kt < Nn; kt += 64) {
        #pragma unroll
        for (int j = 0; j < 2; j++) {
            int i = tid + j*256;
            int d = i >> 4, l4 = i & 15;
            int tau = ((l4 & 7) << 1) | (l4 >> 3);
            int c = tau * 4;
            float a = co[64+d], sh = co[96+d];
            float4 v = *reinterpret_cast<const float4*>(&Kg[(long)d * Nn + kt + c]);
            int base = d*132 + (c & 7)*16 + (c >> 3);
            Ks[base     ] = to_tf32(v.x*a+sh);
            Ks[base + 16] = to_tf32(v.y*a+sh);
            Ks[base + 32] = to_tf32(v.z*a+sh);
            Ks[base + 48] = to_tf32(v.w*a+sh);
        }
        #pragma unroll
        for (int j = 0; j < 8; j++) {
            int i = tid + j*256;
            int kk = i >> 5, lane = i & 31;
            int sig = ((lane & 15) << 1) | (lane >> 4);
            int c = sig * 4;
            float4 v = *reinterpret_cast<const float4*>(&Vtz[(long)(kt + kk) * VD + c]);
            int base = kk*132 + (c & 7)*16 + (c >> 3);
            Vs[base     ] = v.x;
            Vs[base + 16] = v.y;
            Vs[base + 32] = v.z;
            Vs[base + 48] = v.w;
        }
        __syncthreads();

        float sacc[8][4];
        #pragma unroll
        for (int j = 0; j < 8; j++)
            sacc[j][0] = sacc[j][1] = sacc[j][2] = sacc[j][3] = 0.f;
        #pragma unroll
        for (int ksb = 0; ksb < 4; ksb++) {
            int ks = ksb * 8;
            float4 aq = *reinterpret_cast<const float4*>(&Qp[((ksb*8 + w)*32 + l)*4]);
            uint32_t a0 = U(aq.x), a1 = U(aq.y), a2 = U(aq.z), a3 = U(aq.w);
            float4 kL0 = *reinterpret_cast<const float4*>(&Ks[(ks+qc  )*132 + r*16    ]);
            float4 kL1 = *reinterpret_cast<const float4*>(&Ks[(ks+qc  )*132 + r*16 + 4]);
            float4 kH0 = *reinterpret_cast<const float4*>(&Ks[(ks+qc+4)*132 + r*16    ]);
            float4 kH1 = *reinterpret_cast<const float4*>(&Ks[(ks+qc+4)*132 + r*16 + 4]);
            mma_tf32(sacc[0], a0,a1,a2,a3, U(kL0.x),U(kH0.x));
            mma_tf32(sacc[1], a0,a1,a2,a3, U(kL0.y),U(kH0.y));
            mma_tf32(sacc[2], a0,a1,a2,a3, U(kL0.z),U(kH0.z));
            mma_tf32(sacc[3], a0,a1,a2,a3, U(kL0.w),U(kH0.w));
            mma_tf32(sacc[4], a0,a1,a2,a3, U(kL1.x),U(kH1.x));
            mma_tf32(sacc[5], a0,a1,a2,a3, U(kL1.y),U(kH1.y));
            mma_tf32(sacc[6], a0,a1,a2,a3, U(kL1.z),U(kH1.z));
            mma_tf32(sacc[7], a0,a1,a2,a3, U(kL1.w),U(kH1.w));
        }

        float rs0 = 0.f, rs1 = 0.f;
        #pragma unroll
        for (int jn = 0; jn < 8; jn++) {
            sacc[jn][0] = ex2_approx(sacc[jn][0]);
            sacc[jn][1] = ex2_approx(sacc[jn][1]);
            sacc[jn][2] = ex2_approx(sacc[jn][2]);
            sacc[jn][3] = ex2_approx(sacc[jn][3]);
            rs0 += sacc[jn][0] + sacc[jn][1];
            rs1 += sacc[jn][2] + sacc[jn][3];
        }
        rs0 += __shfl_xor_sync(0xffffffffu, rs0, 1);
        rs0 += __shfl_xor_sync(0xffffffffu, rs0, 2);
        rs1 += __shfl_xor_sync(0xffffffffu, rs1, 1);
        rs1 += __shfl_xor_sync(0xffffffffu, rs1, 2);
        l0 += rs0;
        l1 += rs1;

        #pragma unroll
        for (int jn = 0; jn < 8; jn++) {
            int col = jn*8 + 2*qc;
            Ps[(col  )*136 + wq + r    ] = to_tf32(sacc[jn][0]);
            Ps[(col+1)*136 + wq + r    ] = to_tf32(sacc[jn][1]);
            Ps[(col  )*136 + wq + r + 8] = to_tf32(sacc[jn][2]);
            Ps[(col+1)*136 + wq + r + 8] = to_tf32(sacc[jn][3]);
        }
        __syncthreads();

        #pragma unroll
        for (int ks = 0; ks < 64; ks += 8) {
            uint32_t pa[2][4];
            #pragma unroll
            for (int im = 0; im < 2; im++) {
                int cb = qb + im*16;
                pa[im][0] = U(Ps[(ks+qc  )*136 + cb + r    ]);
                pa[im][1] = U(Ps[(ks+qc  )*136 + cb + r + 8]);
                pa[im][2] = U(Ps[(ks+qc+4)*136 + cb + r    ]);
                pa[im][3] = U(Ps[(ks+qc+4)*136 + cb + r + 8]);
            }
            #pragma unroll
            for (int q = 0; q < 2; q++) {
                int qh = 2*e + q;
                float4 vL = *reinterpret_cast<const float4*>(&Vs[(ks+qc  )*132 + r*16 + qh*4]);
                float4 vH = *reinterpret_cast<const float4*>(&Vs[(ks+qc+4)*132 + r*16 + qh*4]);
                #pragma unroll
                for (int im = 0; im < 2; im++) {
                    mma_tf32(oacc[im][q*4+0], pa[im][0],pa[im][1],pa[im][2],pa[im][3], U(vL.x),U(vH.x));
                    mma_tf32(oacc[im][q*4+1], pa[im][0],pa[im][1],pa[im][2],pa[im][3], U(vL.y),U(vH.y));
                    mma_tf32(oacc[im][q*4+2], pa[im][0],pa[im][1],pa[im][2],pa[im][3], U(vL.z),U(vH.z));
                    mma_tf32(oacc[im][q*4+3], pa[im][0],pa[im][1],pa[im][2],pa[im][3], U(vL.w),U(vH.w));
                }
            }
        }
        __syncthreads();
    }

    if (qc == 0) {
        Ls[wq + r    ] = l0;
        Ls[wq + r + 8] = l1;
    }
    __syncthreads();

    // epilogue: normalize, gelu, write o2 channel-major [b][ch][n]
    #pragma unroll
    for (int im = 0; im < 2; im++) {
        float inv0 = 1.f / Ls[qb + im*16 + r    ];
        float inv1 = 1.f / Ls[qb + im*16 + r + 8];
        #pragma unroll
        for (int jn = 0; jn < 8; jn++) {
            int ch = h * VD + e*64 + jn*8 + 2*qc;
            float v0 = gelu_exact(oacc[im][jn][0] * inv0);
            float v1 = gelu_exact(oacc[im][jn][1] * inv0);
            float v2 = gelu_exact(oacc[im][jn][2] * inv1);
            float v3 = gelu_exact(oacc[im][jn][3] * inv1);
            long base = ((long)b * (HEADS*VD) + ch) * Nn + qt + qb + im*16 + r;
            o2[base]          = v0;
            o2[base + Nn]     = v1;
            o2[base + 8]      = v2;
            o2[base + Nn + 8] = v3;
        }
    }
}

// ---------------- BN apply + residual (float4) ----------------
__global__ __launch_bounds__(256) void bn_apply_residual(const float* __restrict__ src, const float* __restrict__ res,
    float* __restrict__ dst, const float* __restrict__ mean, const float* __restrict__ rstd,
    const float* __restrict__ gg, const float* __restrict__ bb, int C, long total4)
{
    const float4* s4 = reinterpret_cast<const float4*>(src);
    const float4* r4 = reinterpret_cast<const float4*>(res);
    float4* d4 = reinterpret_cast<float4*>(dst);
    long stride = (long)gridDim.x * blockDim.x;
    for (long i = (long)blockIdx.x * blockDim.x + threadIdx.x; i < total4; i += stride) {
        int c = (int)((i >> 8) % C);
        float sc = rstd[c] * gg[c];
        float shf = bb[c] - mean[c] * sc;
        float4 v = s4[i]; float4 rr = r4[i];
        v.x = rr.x + v.x * sc + shf; v.y = rr.y + v.y * sc + shf;
        v.z = rr.z + v.z * sc + shf; v.w = rr.w + v.w * sc + shf;
        d4[i] = v;
    }
}

// ---------------- launch ----------------
extern "C" void kernel_launch(void* const* d_in, const int* in_sizes, int n_in,
                              void* d_out, int out_size)
{
    const float* x       = (const float*)d_in[0];
    const float* w_qkv   = (const float*)d_in[1];
    const float* gqkv    = (const float*)d_in[2];
    const float* bqkv    = (const float*)d_in[3];
    const float* w_merge = (const float*)d_in[4];
    const float* gmerge  = (const float*)d_in[5];
    const float* bmerge  = (const float*)d_in[6];
    const float* w_fc1   = (const float*)d_in[7];
    const float* gfc1    = (const float*)d_in[8];
    const float* bfc1    = (const float*)d_in[9];
    const float* w_fc2   = (const float*)d_in[10];
    const float* gfc2    = (const float*)d_in[11];
    const float* bfc2    = (const float*)d_in[12];
    float* out = (float*)d_out;

    float *yb, *vtb, *o2b, *x2b, *h1b, *tmpb, *meanb, *rstdb, *csumb, *csum2b;
    cudaGetSymbolAddress((void**)&yb,     g_y);
    cudaGetSymbolAddress((void**)&vtb,    g_vt);
    cudaGetSymbolAddress((void**)&o2b,    g_o2);
    cudaGetSymbolAddress((void**)&x2b,    g_x2);
    cudaGetSymbolAddress((void**)&h1b,    g_h1);
    cudaGetSymbolAddress((void**)&tmpb,   g_tmp);
    cudaGetSymbolAddress((void**)&meanb,  g_mean);
    cudaGetSymbolAddress((void**)&rstdb,  g_rstd);
    cudaGetSymbolAddress((void**)&csumb,  g_csum);
    cudaGetSymbolAddress((void**)&csum2b, g_csum2);

    static bool attr_done = false;
    if (!attr_done) {
        cudaFuncSetAttribute(flash_att, cudaFuncAttributeMaxDynamicSharedMemorySize, FTOT);
        attr_done = true;
    }

    const float scale = 0.17677669529663687f;

    // 1) qkv conv with fused channel stats
    mm_tf32<0,1><<<dim3(Nn/128, QKV_C/128, Bb), 256>>>(
        w_qkv, x, yb, QKV_C, Nn, Cc, Cc, Nn, (long)Cc*Nn, (long)QKV_C*Nn,
        nullptr, nullptr, nullptr, nullptr, csumb, csum2b);
    bn_finalize<<<(QKV_C+255)/256, 256>>>(csumb, csum2b, meanb, rstdb, QKV_C);
    // 2) V transpose + BN
    transpose_v<<<dim3(Nn/32, VD/32, Bb*HEADS), dim3(32,8)>>>(yb, vtb, meanb, rstdb, gqkv, bqkv);
    // 3) flash attention (+BN on Q,K) + gelu -> o2 channel-major
    flash_att<<<dim3(Nn/128, Bb*HEADS), 256, FTOT>>>(yb, vtb, o2b,
        meanb, rstdb, gqkv, bqkv, scale);
    // 4) merge conv (B = o2, k-major) + fused stats; BN + residual -> x2
    mm_tf32<0,1><<<dim3(Nn/128, Cc/128, Bb), 256>>>(
        w_merge, o2b, tmpb, Cc, Nn, HEADS*VD, HEADS*VD, Nn,
        (long)HEADS*VD*Nn, (long)Cc*Nn, nullptr, nullptr, nullptr, nullptr, csumb, csum2b);
    bn_finalize<<<(Cc+255)/256, 256>>>(csumb, csum2b, meanb, rstdb, Cc);
    bn_apply_residual<<<1024, 256>>>(tmpb, x, x2b, meanb, rstdb, gmerge, bmerge, Cc, (long)Bb*Cc*Nn/4);
    // 5) fc1 + fused stats
    mm_tf32<0,1><<<dim3(Nn/128, FC1_C/128, Bb), 256>>>(
        w_fc1, x2b, tmpb, FC1_C, Nn, Cc, Cc, Nn, (long)Cc*Nn, (long)FC1_C*Nn,
        nullptr, nullptr, nullptr, nullptr, csumb, csum2b);
    bn_finalize<<<(FC1_C+255)/256, 256>>>(csumb, csum2b, meanb, rstdb, FC1_C);
    // 6) fc2 with fc1's BN+gelu fused into B loads + fused stats -> h1b
    mm_tf32<1,1><<<dim3(Nn/128, Cc/128, Bb), 256>>>(
        w_fc2, tmpb, h1b, Cc, Nn, FC1_C, FC1_C, Nn, (long)FC1_C*Nn, (long)Cc*Nn,
        meanb, rstdb, gfc1, bfc1, csumb, csum2b);
    bn_finalize<<<(Cc+255)/256, 256>>>(csumb, csum2b, meanb, rstdb, Cc);
    bn_apply_residual<<<1024, 256>>>(h1b, x2b, out, meanb, rstdb, gfc2, bfc2, Cc, (long)Bb*Cc*Nn/4);
}

// round 13
// speedup vs baseline: 1.0157x; 1.0157x over previous
#include <cuda_runtime.h>
#include <math.h>
#include <stdint.h>

#define Bb 8
#define Cc 384
#define Nn 1024
#define HEADS 8
#define KD 32
#define VD 128
#define QKV_C 1536
#define FC1_C 768
#define EPS 1e-5f

// ---------------- scratch (static device globals; no allocation) ----------------
__device__ float g_y[(long)Bb*QKV_C*Nn];
__device__ float g_vt[(long)Bb*HEADS*Nn*VD];
__device__ float g_o2t[(long)Bb*Nn*HEADS*VD];
__device__ float g_x2[(long)Bb*Cc*Nn];
__device__ float g_h1[(long)Bb*FC1_C*Nn];
__device__ float g_tmp[(long)Bb*FC1_C*Nn];
__device__ float g_mean[QKV_C];
__device__ float g_rstd[QKV_C];
__device__ float g_csum[QKV_C];    // qkv/fc1 stages (finalized + re-zeroed by bn_finalize)
__device__ float g_csum2[QKV_C];
__device__ float g_csM[Cc];        // merge stage sums (consumed inline; zeroed by next qkv)
__device__ float g_csM2[Cc];
__device__ float g_csF[Cc];        // fc2 stage sums
__device__ float g_csF2[Cc];

__device__ __forceinline__ float gelu_exact(float x){
    return 0.5f * x * (1.0f + erff(x * 0.7071067811865476f));
}
__device__ __forceinline__ float to_tf32(float x){
    uint32_t u;
    asm("cvt.rna.tf32.f32 %0, %1;" : "=r"(u) : "f"(x));
    return __uint_as_float(u);
}
__device__ __forceinline__ float ex2_approx(float x){
    float y;
    asm("ex2.approx.ftz.f32 %0, %1;" : "=f"(y) : "f"(x));
    return y;
}
__device__ __forceinline__ void mma_tf32(float c[4],
    uint32_t a0, uint32_t a1, uint32_t a2, uint32_t a3, uint32_t b0, uint32_t b1)
{
    asm volatile("mma.sync.aligned.m16n8k8.row.col.f32.tf32.tf32.f32 "
        "{%0,%1,%2,%3}, {%4,%5,%6,%7}, {%8,%9}, {%0,%1,%2,%3};"
        : "+f"(c[0]), "+f"(c[1]), "+f"(c[2]), "+f"(c[3])
        : "r"(a0), "r"(a1), "r"(a2), "r"(a3), "r"(b0), "r"(b1));
}
#define U(f) __float_as_uint(f)

// =====================================================================
// Unified tf32 GEMM — R11 version exactly (best measured), plus ZEROST:
// block (0,0,0) zeroes the merge/fc2 stage sum buffers for graph replay.
// =====================================================================
#define SMS 136

template<int AMODE,int BMODE,int BNB,int STATS,int ZEROST>
__global__ __launch_bounds__(256,2) void mm_tf32(
    const float* __restrict__ A, const float* __restrict__ B, float* __restrict__ C,
    int M, int N, int K, int lda, int ldb,
    long strideB, long strideC,
    const float* __restrict__ bnM, const float* __restrict__ bnR,
    const float* __restrict__ bnG, const float* __restrict__ bnBv,
    float* __restrict__ gS, float* __restrict__ gS2)
{
    __shared__ __align__(16) float As[2][16][SMS];
    __shared__ __align__(16) float Bs[2][16][SMS];

    const int tid = threadIdx.x;
    if (ZEROST && blockIdx.x == 0 && blockIdx.y == 0 && blockIdx.z == 0) {
        for (int i = tid; i < Cc; i += 256) {
            g_csM[i] = 0.f; g_csM2[i] = 0.f;
            g_csF[i] = 0.f; g_csF2[i] = 0.f;
        }
    }

    const int z = blockIdx.z;
    const float* Ab = A;
    const float* Bc = B + (long)z * strideB;
    float* Cz = C + (long)z * strideC;

    const int bm = blockIdx.y * 128, bn = blockIdx.x * 128;
    const int w = tid >> 5, l = tid & 31;
    const int wm = (w >> 1) * 32, wn = (w & 1) * 64;
    const int r = l >> 2, qc = l & 3;

    float acc[2][8][4];
    #pragma unroll
    for (int i = 0; i < 2; i++)
        #pragma unroll
        for (int j = 0; j < 8; j++)
            #pragma unroll
            for (int k = 0; k < 4; k++) acc[i][j][k] = 0.f;

    float4 ra[2], rb[2];

    auto gload = [&](int k0){
        #pragma unroll
        for (int j = 0; j < 2; j++){
            int i = tid + j*256;
            if (AMODE == 0) { int row = i >> 2, kq = (i & 3) * 4;
                ra[j] = *reinterpret_cast<const float4*>(&Ab[(long)(bm+row)*lda + k0+kq]); }
            else            { int kk = i >> 5, mq = (i & 31) * 4;
                ra[j] = *reinterpret_cast<const float4*>(&Ab[(long)(k0+kk)*lda + bm+mq]); }
        }
        #pragma unroll
        for (int j = 0; j < 2; j++){
            int i = tid + j*256;
            if (BMODE == 0) { int kk = i >> 5, nq = (i & 31) * 4;
                rb[j] = *reinterpret_cast<const float4*>(&Bc[(long)(k0+kk)*ldb + bn+nq]);
                if (BNB) {
                    int c = k0 + kk;
                    float a = bnR[c]*bnG[c];
                    float sh = bnBv[c] - bnM[c]*a;
                    rb[j].x = gelu_exact(rb[j].x*a+sh);
                    rb[j].y = gelu_exact(rb[j].y*a+sh);
                    rb[j].z = gelu_exact(rb[j].z*a+sh);
                    rb[j].w = gelu_exact(rb[j].w*a+sh);
                } }
            else            { int row = i >> 2, kq = (i & 3) * 4;
                rb[j] = *reinterpret_cast<const float4*>(&Bc[(long)(bn+row)*ldb + k0+kq]); }
        }
    };

    auto sstore = [&](int buf){
        #pragma unroll
        for (int j = 0; j < 2; j++){
            int i = tid + j*256;
            if (AMODE == 0) { int row = i >> 2, kq = (i & 3) * 4;
                As[buf][kq+0][row] = to_tf32(ra[j].x);
                As[buf][kq+1][row] = to_tf32(ra[j].y);
                As[buf][kq+2][row] = to_tf32(ra[j].z);
                As[buf][kq+3][row] = to_tf32(ra[j].w); }
            else            { int kk = i >> 5, mq = (i & 31) * 4;
                As[buf][kk][mq+0] = to_tf32(ra[j].x);
                As[buf][kk][mq+1] = to_tf32(ra[j].y);
                As[buf][kk][mq+2] = to_tf32(ra[j].z);
                As[buf][kk][mq+3] = to_tf32(ra[j].w); }
        }
        #pragma unroll
        for (int j = 0; j < 2; j++){
            int i = tid + j*256;
            if (BMODE == 0) { int kk = i >> 5, nq = (i & 31) * 4;
                Bs[buf][kk][nq+0] = to_tf32(rb[j].x);
                Bs[buf][kk][nq+1] = to_tf32(rb[j].y);
                Bs[buf][kk][nq+2] = to_tf32(rb[j].z);
                Bs[buf][kk][nq+3] = to_tf32(rb[j].w); }
            else            { int row = i >> 2, kq = (i & 3) * 4;
                Bs[buf][kq+0][row] = to_tf32(rb[j].x);
                Bs[buf][kq+1][row] = to_tf32(rb[j].y);
                Bs[buf][kq+2][row] = to_tf32(rb[j].z);
                Bs[buf][kq+3][row] = to_tf32(rb[j].w); }
        }
    };

    auto compute = [&](int buf){
        #pragma unroll
        for (int ks = 0; ks < 16; ks += 8){
            uint32_t af[2][4], bf[8][2];
            #pragma unroll
            for (int im = 0; im < 2; im++){
                af[im][0] = U(As[buf][ks+qc  ][wm+im*16+r  ]);
                af[im][1] = U(As[buf][ks+qc  ][wm+im*16+r+8]);
                af[im][2] = U(As[buf][ks+qc+4][wm+im*16+r  ]);
                af[im][3] = U(As[buf][ks+qc+4][wm+im*16+r+8]);
            }
            #pragma unroll
            for (int jn = 0; jn < 8; jn++){
                bf[jn][0] = U(Bs[buf][ks+qc  ][wn+jn*8+r]);
                bf[jn][1] = U(Bs[buf][ks+qc+4][wn+jn*8+r]);
            }
            #pragma unroll
            for (int im = 0; im < 2; im++)
                #pragma unroll
                for (int jn = 0; jn < 8; jn++)
                    mma_tf32(acc[im][jn], af[im][0], af[im][1], af[im][2], af[im][3],
                             bf[jn][0], bf[jn][1]);
        }
    };

    gload(0); sstore(0); __syncthreads();
    int buf = 0;
    for (int k0 = 0; k0 < K; k0 += 16){
        bool more = (k0 + 16) < K;
        if (more) gload(k0 + 16);
        compute(buf);
        if (more) { sstore(buf ^ 1); buf ^= 1; }
        __syncthreads();
    }

    #pragma unroll
    for (int im = 0; im < 2; im++){
        float sl = 0.f, s2l = 0.f, shv = 0.f, s2h = 0.f;
        #pragma unroll
        for (int jn = 0; jn < 8; jn++){
            float v0 = acc[im][jn][0], v1 = acc[im][jn][1];
            float v2 = acc[im][jn][2], v3 = acc[im][jn][3];
            int row = bm + wm + im*16 + r;
            int col = bn + wn + jn*8 + 2*qc;
            *reinterpret_cast<float2*>(&Cz[(long)row * N + col])     = make_float2(v0, v1);
            *reinterpret_cast<float2*>(&Cz[(long)(row+8) * N + col]) = make_float2(v2, v3);
            if (STATS) {
                sl  += v0 + v1;       s2l += v0*v0 + v1*v1;
                shv += v2 + v3;       s2h += v2*v2 + v3*v3;
            }
        }
        if (STATS) {
            sl  += __shfl_xor_sync(0xffffffffu, sl, 1);
            sl  += __shfl_xor_sync(0xffffffffu, sl, 2);
            s2l += __shfl_xor_sync(0xffffffffu, s2l, 1);
            s2l += __shfl_xor_sync(0xffffffffu, s2l, 2);
            shv += __shfl_xor_sync(0xffffffffu, shv, 1);
            shv += __shfl_xor_sync(0xffffffffu, shv, 2);
            s2h += __shfl_xor_sync(0xffffffffu, s2h, 1);
            s2h += __shfl_xor_sync(0xffffffffu, s2h, 2);
            if (qc == 0) {
                int row = bm + wm + im*16 + r;
                atomicAdd(&gS[row],    sl);
                atomicAdd(&gS2[row],   s2l);
                atomicAdd(&gS[row+8],  shv);
                atomicAdd(&gS2[row+8], s2h);
            }
        }
    }
}

// ---------------- BN finalize (qkv/fc1 stages): mean/rstd; re-zero sums ----------
__global__ void bn_finalize(float* __restrict__ sum, float* __restrict__ sum2,
                            float* __restrict__ mean, float* __restrict__ rstd, int C)
{
    int c = blockIdx.x * blockDim.x + threadIdx.x;
    if (c < C) {
        const float inv = 1.0f / (float)(Bb * Nn);
        float m = sum[c] * inv;
        float v = sum2[c] * inv - m * m;
        mean[c] = m;
        rstd[c] = rsqrtf(v + EPS);
        sum[c] = 0.f;
        sum2[c] = 0.f;
    }
}

// =====================================================================
// V transpose + BN
// =====================================================================
__global__ __launch_bounds__(256) void transpose_v(const float* __restrict__ y,
    float* __restrict__ vt,
    const float* __restrict__ mean, const float* __restrict__ rstd,
    const float* __restrict__ gg, const float* __restrict__ bbias)
{
    __shared__ float t[32][33];
    const int z = blockIdx.z, b = z >> 3, h = z & 7;
    const float* V = y + ((long)b * QKV_C + h * 192 + 64) * Nn;
    const int n0 = blockIdx.x * 32, d0 = blockIdx.y * 32;
    const int tx = threadIdx.x, ty = threadIdx.y;  // 32 x 8
    #pragma unroll
    for (int j = 0; j < 4; j++){
        int d = d0 + ty + j*8;
        int ch = h*192 + 64 + d;
        float a = rstd[ch]*gg[ch];
        float sh = bbias[ch] - mean[ch]*a;
        t[ty + j*8][tx] = V[(long)d * Nn + n0 + tx] * a + sh;
    }
    __syncthreads();
    float* dst = vt + (long)z * Nn * VD;
    #pragma unroll
    for (int j = 0; j < 4; j++)
        dst[(long)(n0 + ty + j*8) * VD + d0 + tx] = to_tf32(t[tx][ty + j*8]);
}

// =====================================================================
// Flash attention — R11 core, tile loader batched: all 10 LDG.128 issued
// into locals first (MLP~10), then all STS. Staging regs die before the
// S-phase MMAs (no live range across MMA blocks -> no R9-style spill).
// =====================================================================
#define FQ  0
#define FK  (4*8*32*4)
#define FV  (FK + 32*132)
#define FP  (FV + 64*132)
#define FCO (FP + 64*136)
#define FLS (FCO + 128)
#define FTOT ((FLS + 128) * 4)

__global__ __launch_bounds__(256,2) void flash_att(
    const float* __restrict__ y, const float* __restrict__ vt,
    float* __restrict__ o2t,
    const float* __restrict__ mean, const float* __restrict__ rstd,
    const float* __restrict__ gg, const float* __restrict__ bbias,
    float scale)
{
    extern __shared__ float sm[];
    float* Qp = sm + FQ;
    float* Ks = sm + FK;
    float* Vs = sm + FV;
    float* Ps = sm + FP;
    float* co = sm + FCO;
    float* Ls = sm + FLS;

    const int z = blockIdx.y, b = z >> 3, h = z & 7;
    const float* Q   = y + ((long)b * QKV_C + h * 192) * Nn;
    const float* Kg  = Q + 32 * Nn;
    const float* Vtz = vt + (long)z * Nn * VD;
    const int qt = blockIdx.x * 128;
    const int tid = threadIdx.x, w = tid >> 5, l = tid & 31;
    const int r = l >> 2, qc = l & 3;
    const int wq = w * 16;
    const int g = w >> 1, e = w & 1;
    const int qb = g * 32;

    if (tid < 32) {
        int ch = h*192 + tid;
        float a = rstd[ch]*gg[ch]*scale*1.44269504088896f;
        co[tid]    = a;
        co[32+tid] = (bbias[ch] - mean[ch]*rstd[ch]*gg[ch])*scale*1.44269504088896f;
    } else if (tid < 64) {
        int d = tid - 32;
        int ch = h*192 + 32 + d;
        float a = rstd[ch]*gg[ch];
        co[64+d] = a;
        co[96+d] = bbias[ch] - mean[ch]*a;
    }
    __syncthreads();

    for (int i = tid; i < 32*32; i += 256) {
        int d = i >> 5, c = (i & 31) * 4;
        float a = co[d], sh = co[32+d];
        float4 v = *reinterpret_cast<const float4*>(&Q[(long)d * Nn + qt + c]);
        float vv[4] = { to_tf32(v.x*a+sh), to_tf32(v.y*a+sh),
                        to_tf32(v.z*a+sh), to_tf32(v.w*a+sh) };
        int ksb = d >> 3, dd = d & 7;
        int qcc = dd & 3, jhi = dd >> 2;
        #pragma unroll
        for (int t = 0; t < 4; t++) {
            int q = c + t;
            int ww = q >> 4, qq = q & 15;
            int rr = qq & 7, jlo = qq >> 3;
            Qp[(((ksb*8 + ww)*32) + rr*4 + qcc)*4 + jhi*2 + jlo] = vv[t];
        }
    }

    // precomputed loader lane mappings
    const int kld_d0 = tid >> 4;
    const int kld_l4 = tid & 15;
    const int kld_c  = ((((kld_l4 & 7) << 1) | (kld_l4 >> 3))) * 4;
    const int vld_kk0 = tid >> 5;
    const int vld_lane = tid & 31;
    const int vld_c = ((((vld_lane & 15) << 1) | (vld_lane >> 4))) * 4;

    float oacc[2][8][4];
    #pragma unroll
    for (int im = 0; im < 2; im++)
        #pragma unroll
        for (int j = 0; j < 8; j++)
            oacc[im][j][0] = oacc[im][j][1] = oacc[im][j][2] = oacc[im][j][3] = 0.f;
    float l0 = 0.f, l1 = 0.f;

    for (int kt = 0; kt < Nn; kt += 64) {
        // ---- batched loads: all LDGs first (MLP ~10), then all stores ----
        {
            float4 kr0 = *reinterpret_cast<const float4*>(&Kg[(long)kld_d0 * Nn + kt + kld_c]);
            float4 kr1 = *reinterpret_cast<const float4*>(&Kg[(long)(kld_d0+16) * Nn + kt + kld_c]);
            float4 vr[8];
            #pragma unroll
            for (int j = 0; j < 8; j++)
                vr[j] = *reinterpret_cast<const float4*>(&Vtz[(long)(kt + vld_kk0 + j*8) * VD + vld_c]);

            {
                float a = co[64+kld_d0], sh = co[96+kld_d0];
                int base = kld_d0*132 + (kld_c & 7)*16 + (kld_c >> 3);
                Ks[base     ] = to_tf32(kr0.x*a+sh);
                Ks[base + 16] = to_tf32(kr0.y*a+sh);
                Ks[base + 32] = to_tf32(kr0.z*a+sh);
                Ks[base + 48] = to_tf32(kr0.w*a+sh);
            }
            {
                int d = kld_d0 + 16;
                float a = co[64+d], sh = co[96+d];
                int base = d*132 + (kld_c & 7)*16 + (kld_c >> 3);
                Ks[base     ] = to_tf32(kr1.x*a+sh);
                Ks[base + 16] = to_tf32(kr1.y*a+sh);
                Ks[base + 32] = to_tf32(kr1.z*a+sh);
                Ks[base + 48] = to_tf32(kr1.w*a+sh);
            }
            #pragma unroll
            for (int j = 0; j < 8; j++) {
                int kk = vld_kk0 + j*8;
                int base = kk*132 + (vld_c & 7)*16 + (vld_c >> 3);
                Vs[base     ] = vr[j].x;
                Vs[base + 16] = vr[j].y;
                Vs[base + 32] = vr[j].z;
                Vs[base + 48] = vr[j].w;
            }
        }
        __syncthreads();

        float sacc[8][4];
        #pragma unroll
        for (int j = 0; j < 8; j++)
            sacc[j][0] = sacc[j][1] = sacc[j][2] = sacc[j][3] = 0.f;
        #pragma unroll
        for (int ksb = 0; ksb < 4; ksb++) {
            int ks = ksb * 8;
            float4 aq = *reinterpret_cast<const float4*>(&Qp[((ksb*8 + w)*32 + l)*4]);
            uint32_t a0 = U(aq.x), a1 = U(aq.y), a2 = U(aq.z), a3 = U(aq.w);
            float4 kL0 = *reinterpret_cast<const float4*>(&Ks[(ks+qc  )*132 + r*16    ]);
            float4 kL1 = *reinterpret_cast<const float4*>(&Ks[(ks+qc  )*132 + r*16 + 4]);
            float4 kH0 = *reinterpret_cast<const float4*>(&Ks[(ks+qc+4)*132 + r*16    ]);
            float4 kH1 = *reinterpret_cast<const float4*>(&Ks[(ks+qc+4)*132 + r*16 + 4]);
            mma_tf32(sacc[0], a0,a1,a2,a3, U(kL0.x),U(kH0.x));
            mma_tf32(sacc[1], a0,a1,a2,a3, U(kL0.y),U(kH0.y));
            mma_tf32(sacc[2], a0,a1,a2,a3, U(kL0.z),U(kH0.z));
            mma_tf32(sacc[3], a0,a1,a2,a3, U(kL0.w),U(kH0.w));
            mma_tf32(sacc[4], a0,a1,a2,a3, U(kL1.x),U(kH1.x));
            mma_tf32(sacc[5], a0,a1,a2,a3, U(kL1.y),U(kH1.y));
            mma_tf32(sacc[6], a0,a1,a2,a3, U(kL1.z),U(kH1.z));
            mma_tf32(sacc[7], a0,a1,a2,a3, U(kL1.w),U(kH1.w));
        }

        float rs0 = 0.f, rs1 = 0.f;
        #pragma unroll
        for (int jn = 0; jn < 8; jn++) {
            sacc[jn][0] = ex2_approx(sacc[jn][0]);
            sacc[jn][1] = ex2_approx(sacc[jn][1]);
            sacc[jn][2] = ex2_approx(sacc[jn][2]);
            sacc[jn][3] = ex2_approx(sacc[jn][3]);
            rs0 += sacc[jn][0] + sacc[jn][1];
            rs1 += sacc[jn][2] + sacc[jn][3];
        }
        rs0 += __shfl_xor_sync(0xffffffffu, rs0, 1);
        rs0 += __shfl_xor_sync(0xffffffffu, rs0, 2);
        rs1 += __shfl_xor_sync(0xffffffffu, rs1, 1);
        rs1 += __shfl_xor_sync(0xffffffffu, rs1, 2);
        l0 += rs0;
        l1 += rs1;

        #pragma unroll
        for (int jn = 0; jn < 8; jn++) {
            int col = jn*8 + 2*qc;
            Ps[(col  )*136 + wq + r    ] = to_tf32(sacc[jn][0]);
            Ps[(col+1)*136 + wq + r    ] = to_tf32(sacc[jn][1]);
            Ps[(col  )*136 + wq + r + 8] = to_tf32(sacc[jn][2]);
            Ps[(col+1)*136 + wq + r + 8] = to_tf32(sacc[jn][3]);
        }
        __syncthreads();

        #pragma unroll
        for (int ks = 0; ks < 64; ks += 8) {
            uint32_t pa[2][4];
            #pragma unroll
            for (int im = 0; im < 2; im++) {
                int cb = qb + im*16;
                pa[im][0] = U(Ps[(ks+qc  )*136 + cb + r    ]);
                pa[im][1] = U(Ps[(ks+qc  )*136 + cb + r + 8]);
                pa[im][2] = U(Ps[(ks+qc+4)*136 + cb + r    ]);
                pa[im][3] = U(Ps[(ks+qc+4)*136 + cb + r + 8]);
            }
            #pragma unroll
            for (int q = 0; q < 2; q++) {
                int qh = 2*e + q;
                float4 vL = *reinterpret_cast<const float4*>(&Vs[(ks+qc  )*132 + r*16 + qh*4]);
                float4 vH = *reinterpret_cast<const float4*>(&Vs[(ks+qc+4)*132 + r*16 + qh*4]);
                #pragma unroll
                for (int im = 0; im < 2; im++) {
                    mma_tf32(oacc[im][q*4+0], pa[im][0],pa[im][1],pa[im][2],pa[im][3], U(vL.x),U(vH.x));
                    mma_tf32(oacc[im][q*4+1], pa[im][0],pa[im][1],pa[im][2],pa[im][3], U(vL.y),U(vH.y));
                    mma_tf32(oacc[im][q*4+2], pa[im][0],pa[im][1],pa[im][2],pa[im][3], U(vL.z),U(vH.z));
                    mma_tf32(oacc[im][q*4+3], pa[im][0],pa[im][1],pa[im][2],pa[im][3], U(vL.w),U(vH.w));
                }
            }
        }
        __syncthreads();
    }

    if (qc == 0) {
        Ls[wq + r    ] = l0;
        Ls[wq + r + 8] = l1;
    }
    __syncthreads();

    #pragma unroll
    for (int im = 0; im < 2; im++) {
        float inv0 = 1.f / Ls[qb + im*16 + r    ];
        float inv1 = 1.f / Ls[qb + im*16 + r + 8];
        #pragma unroll
        for (int jn = 0; jn < 8; jn++) {
            int ch = h * VD + e*64 + jn*8 + 2*qc;
            float v0 = gelu_exact(oacc[im][jn][0] * inv0);
            float v1 = gelu_exact(oacc[im][jn][1] * inv0);
            float v2 = gelu_exact(oacc[im][jn][2] * inv1);
            float v3 = gelu_exact(oacc[im][jn][3] * inv1);
            long base = ((long)b * Nn + qt + qb + im*16 + r) * (long)(HEADS*VD) + ch;
            *reinterpret_cast<float2*>(&o2t[base]) = make_float2(v0, v1);
            *reinterpret_cast<float2*>(&o2t[base + 8L*(HEADS*VD)]) = make_float2(v2, v3);
        }
    }
}

// ---------------- BN apply + residual with inline finalize from raw sums --------
__global__ __launch_bounds__(256) void bn_apply_residual_stats(
    const float* __restrict__ src, const float* __restrict__ res,
    float* __restrict__ dst, const float* __restrict__ sum, const float* __restrict__ sum2,
    const float* __restrict__ gg, const float* __restrict__ bb, int C, long total4)
{
    const float4* s4 = reinterpret_cast<const float4*>(src);
    const float4* r4 = reinterpret_cast<const float4*>(res);
    float4* d4 = reinterpret_cast<float4*>(dst);
    const float inv = 1.0f / (float)(Bb * Nn);
    long stride = (long)gridDim.x * blockDim.x;
    for (long i = (long)blockIdx.x * blockDim.x + threadIdx.x; i < total4; i += stride) {
        int c = (int)((i >> 8) % C);
        float m = sum[c] * inv;
        float var = sum2[c] * inv - m * m;
        float rstd = rsqrtf(var + EPS);
        float sc = rstd * gg[c];
        float shf = bb[c] - m * sc;
        float4 v = s4[i]; float4 rr = r4[i];
        v.x = rr.x + v.x * sc + shf; v.y = rr.y + v.y * sc + shf;
        v.z = rr.z + v.z * sc + shf; v.w = rr.w + v.w * sc + shf;
        d4[i] = v;
    }
}

// ---------------- launch ----------------
extern "C" void kernel_launch(void* const* d_in, const int* in_sizes, int n_in,
                              void* d_out, int out_size)
{
    const float* x       = (const float*)d_in[0];
    const float* w_qkv   = (const float*)d_in[1];
    const float* gqkv    = (const float*)d_in[2];
    const float* bqkv    = (const float*)d_in[3];
    const float* w_merge = (const float*)d_in[4];
    const float* gmerge  = (const float*)d_in[5];
    const float* bmerge  = (const float*)d_in[6];
    const float* w_fc1   = (const float*)d_in[7];
    const float* gfc1    = (const float*)d_in[8];
    const float* bfc1    = (const float*)d_in[9];
    const float* w_fc2   = (const float*)d_in[10];
    const float* gfc2    = (const float*)d_in[11];
    const float* bfc2    = (const float*)d_in[12];
    float* out = (float*)d_out;

    float *yb, *vtb, *o2tb, *x2b, *h1b, *tmpb, *meanb, *rstdb, *csumb, *csum2b;
    float *csMb, *csM2b, *csFb, *csF2b;
    cudaGetSymbolAddress((void**)&yb,     g_y);
    cudaGetSymbolAddress((void**)&vtb,    g_vt);
    cudaGetSymbolAddress((void**)&o2tb,   g_o2t);
    cudaGetSymbolAddress((void**)&x2b,    g_x2);
    cudaGetSymbolAddress((void**)&h1b,    g_h1);
    cudaGetSymbolAddress((void**)&tmpb,   g_tmp);
    cudaGetSymbolAddress((void**)&meanb,  g_mean);
    cudaGetSymbolAddress((void**)&rstdb,  g_rstd);
    cudaGetSymbolAddress((void**)&csumb,  g_csum);
    cudaGetSymbolAddress((void**)&csum2b, g_csum2);
    cudaGetSymbolAddress((void**)&csMb,   g_csM);
    cudaGetSymbolAddress((void**)&csM2b,  g_csM2);
    cudaGetSymbolAddress((void**)&csFb,   g_csF);
    cudaGetSymbolAddress((void**)&csF2b,  g_csF2);

    static bool attr_done = false;
    if (!attr_done) {
        cudaFuncSetAttribute(flash_att, cudaFuncAttributeMaxDynamicSharedMemorySize, FTOT);
        attr_done = true;
    }

    const float scale = 0.17677669529663687f;

    // 1) qkv conv + fused stats (+replay re-zero of merge/fc2 sum buffers)
    mm_tf32<0,0,0,1,1><<<dim3(Nn/128, QKV_C/128, Bb), 256>>>(
        w_qkv, x, yb, QKV_C, Nn, Cc, Cc, Nn, (long)Cc*Nn, (long)QKV_C*Nn,
        nullptr, nullptr, nullptr, nullptr, csumb, csum2b);
    bn_finalize<<<(QKV_C+255)/256, 256>>>(csumb, csum2b, meanb, rstdb, QKV_C);
    // 2) V transpose + BN
    transpose_v<<<dim3(Nn/32, VD/32, Bb*HEADS), dim3(32,8)>>>(yb, vtb, meanb, rstdb, gqkv, bqkv);
    // 3) flash attention (+BN on Q,K) + gelu
    flash_att<<<dim3(Nn/128, Bb*HEADS), 256, FTOT>>>(yb, vtb, o2tb,
        meanb, rstdb, gqkv, bqkv, scale);
    // 4) merge conv + fused stats (into csM); apply inline-finalized BN + residual
    mm_tf32<0,1,0,1,0><<<dim3(Nn/128, Cc/128, Bb), 256>>>(
        w_merge, o2tb, tmpb, Cc, Nn, HEADS*VD, HEADS*VD, HEADS*VD,
        (long)Nn*HEADS*VD, (long)Cc*Nn, nullptr, nullptr, nullptr, nullptr, csMb, csM2b);
    bn_apply_residual_stats<<<1024, 256>>>(tmpb, x, x2b, csMb, csM2b, gmerge, bmerge, Cc, (long)Bb*Cc*Nn/4);
    // 5) fc1 + fused stats
    mm_tf32<0,0,0,1,0><<<dim3(Nn/128, FC1_C/128, Bb), 256>>>(
        w_fc1, x2b, tmpb, FC1_C, Nn, Cc, Cc, Nn, (long)Cc*Nn, (long)FC1_C*Nn,
        nullptr, nullptr, nullptr, nullptr, csumb, csum2b);
    bn_finalize<<<(FC1_C+255)/256, 256>>>(csumb, csum2b, meanb, rstdb, FC1_C);
    // 6) fc2 with fc1's BN+gelu fused into B loads + fused stats (into csF)
    mm_tf32<0,0,1,1,0><<<dim3(Nn/128, Cc/128, Bb), 256>>>(
        w_fc2, tmpb, h1b, Cc, Nn, FC1_C, FC1_C, Nn, (long)FC1_C*Nn, (long)Cc*Nn,
        meanb, rstdb, gfc1, bfc1, csFb, csF2b);
    bn_apply_residual_stats<<<1024, 256>>>(h1b, x2b, out, csFb, csF2b, gfc2, bfc2, Cc, (long)Bb*Cc*Nn/4);
}

// round 14
// speedup vs baseline: 1.0276x; 1.0117x over previous
#include <cuda_runtime.h>
#include <math.h>
#include <stdint.h>

#define Bb 8
#define Cc 384
#define Nn 1024
#define HEADS 8
#define KD 32
#define VD 128
#define QKV_C 1536
#define FC1_C 768
#define EPS 1e-5f
#define INV_BN (1.0f/8192.0f)

// ---------------- scratch (static device globals; no allocation) ----------------
__device__ float g_y[(long)Bb*QKV_C*Nn];
__device__ float g_vt[(long)Bb*HEADS*Nn*VD];
__device__ float g_o2t[(long)Bb*Nn*HEADS*VD];
__device__ float g_x2[(long)Bb*Cc*Nn];
__device__ float g_h1[(long)Bb*FC1_C*Nn];
__device__ float g_tmp[(long)Bb*FC1_C*Nn];
__device__ float g_csQ[QKV_C];   // qkv sums: consumed by transpose_v/flash; zeroed by final apply
__device__ float g_csQ2[QKV_C];
__device__ float g_cs1[FC1_C];   // fc1 sums: consumed by fc2 loader; zeroed by qkv ZEROST
__device__ float g_cs1_2[FC1_C];
__device__ float g_csM[Cc];      // merge sums: consumed by apply; zeroed by qkv ZEROST
__device__ float g_csM2[Cc];
__device__ float g_csF[Cc];      // fc2 sums: consumed by final apply; zeroed by qkv ZEROST
__device__ float g_csF2[Cc];

__device__ __forceinline__ float gelu_exact(float x){
    return 0.5f * x * (1.0f + erff(x * 0.7071067811865476f));
}
__device__ __forceinline__ float to_tf32(float x){
    uint32_t u;
    asm("cvt.rna.tf32.f32 %0, %1;" : "=r"(u) : "f"(x));
    return __uint_as_float(u);
}
__device__ __forceinline__ float ex2_approx(float x){
    float y;
    asm("ex2.approx.ftz.f32 %0, %1;" : "=f"(y) : "f"(x));
    return y;
}
__device__ __forceinline__ void mma_tf32(float c[4],
    uint32_t a0, uint32_t a1, uint32_t a2, uint32_t a3, uint32_t b0, uint32_t b1)
{
    asm volatile("mma.sync.aligned.m16n8k8.row.col.f32.tf32.tf32.f32 "
        "{%0,%1,%2,%3}, {%4,%5,%6,%7}, {%8,%9}, {%0,%1,%2,%3};"
        : "+f"(c[0]), "+f"(c[1]), "+f"(c[2]), "+f"(c[3])
        : "r"(a0), "r"(a1), "r"(a2), "r"(a3), "r"(b0), "r"(b1));
}
#define U(f) __float_as_uint(f)

// =====================================================================
// Unified tf32 GEMM — R11 body exactly. BNB=1: BN(from raw sums)+gelu on
// B at load. STATS=1: per-row sum atomics. ZEROST=1: block(0,0,0) zeroes
// downstream-stage sum buffers for graph replay (race-free: those buffers
// are only produced/consumed by later kernels).
// =====================================================================
#define SMS 136

template<int AMODE,int BMODE,int BNB,int STATS,int ZEROST>
__global__ __launch_bounds__(256,2) void mm_tf32(
    const float* __restrict__ A, const float* __restrict__ B, float* __restrict__ C,
    int M, int N, int K, int lda, int ldb,
    long strideB, long strideC,
    const float* __restrict__ bnS, const float* __restrict__ bnS2,
    const float* __restrict__ bnG, const float* __restrict__ bnBv,
    float* __restrict__ gS, float* __restrict__ gS2)
{
    __shared__ __align__(16) float As[2][16][SMS];
    __shared__ __align__(16) float Bs[2][16][SMS];

    const int tid = threadIdx.x;
    if (ZEROST && blockIdx.x == 0 && blockIdx.y == 0 && blockIdx.z == 0) {
        for (int i = tid; i < FC1_C; i += 256) { g_cs1[i] = 0.f; g_cs1_2[i] = 0.f; }
        for (int i = tid; i < Cc; i += 256) {
            g_csM[i] = 0.f; g_csM2[i] = 0.f;
            g_csF[i] = 0.f; g_csF2[i] = 0.f;
        }
    }

    const int z = blockIdx.z;
    const float* Ab = A;
    const float* Bc = B + (long)z * strideB;
    float* Cz = C + (long)z * strideC;

    const int bm = blockIdx.y * 128, bn = blockIdx.x * 128;
    const int w = tid >> 5, l = tid & 31;
    const int wm = (w >> 1) * 32, wn = (w & 1) * 64;
    const int r = l >> 2, qc = l & 3;

    float acc[2][8][4];
    #pragma unroll
    for (int i = 0; i < 2; i++)
        #pragma unroll
        for (int j = 0; j < 8; j++)
            #pragma unroll
            for (int k = 0; k < 4; k++) acc[i][j][k] = 0.f;

    float4 ra[2], rb[2];

    auto gload = [&](int k0){
        #pragma unroll
        for (int j = 0; j < 2; j++){
            int i = tid + j*256;
            if (AMODE == 0) { int row = i >> 2, kq = (i & 3) * 4;
                ra[j] = *reinterpret_cast<const float4*>(&Ab[(long)(bm+row)*lda + k0+kq]); }
            else            { int kk = i >> 5, mq = (i & 31) * 4;
                ra[j] = *reinterpret_cast<const float4*>(&Ab[(long)(k0+kk)*lda + bm+mq]); }
        }
        #pragma unroll
        for (int j = 0; j < 2; j++){
            int i = tid + j*256;
            if (BMODE == 0) { int kk = i >> 5, nq = (i & 31) * 4;
                rb[j] = *reinterpret_cast<const float4*>(&Bc[(long)(k0+kk)*ldb + bn+nq]);
                if (BNB) {
                    int c = k0 + kk;
                    float m = bnS[c]*INV_BN;
                    float var = bnS2[c]*INV_BN - m*m;
                    float a = rsqrtf(var + EPS)*bnG[c];
                    float sh = bnBv[c] - m*a;
                    rb[j].x = gelu_exact(rb[j].x*a+sh);
                    rb[j].y = gelu_exact(rb[j].y*a+sh);
                    rb[j].z = gelu_exact(rb[j].z*a+sh);
                    rb[j].w = gelu_exact(rb[j].w*a+sh);
                } }
            else            { int row = i >> 2, kq = (i & 3) * 4;
                rb[j] = *reinterpret_cast<const float4*>(&Bc[(long)(bn+row)*ldb + k0+kq]); }
        }
    };

    auto sstore = [&](int buf){
        #pragma unroll
        for (int j = 0; j < 2; j++){
            int i = tid + j*256;
            if (AMODE == 0) { int row = i >> 2, kq = (i & 3) * 4;
                As[buf][kq+0][row] = to_tf32(ra[j].x);
                As[buf][kq+1][row] = to_tf32(ra[j].y);
                As[buf][kq+2][row] = to_tf32(ra[j].z);
                As[buf][kq+3][row] = to_tf32(ra[j].w); }
            else            { int kk = i >> 5, mq = (i & 31) * 4;
                As[buf][kk][mq+0] = to_tf32(ra[j].x);
                As[buf][kk][mq+1] = to_tf32(ra[j].y);
                As[buf][kk][mq+2] = to_tf32(ra[j].z);
                As[buf][kk][mq+3] = to_tf32(ra[j].w); }
        }
        #pragma unroll
        for (int j = 0; j < 2; j++){
            int i = tid + j*256;
            if (BMODE == 0) { int kk = i >> 5, nq = (i & 31) * 4;
                Bs[buf][kk][nq+0] = to_tf32(rb[j].x);
                Bs[buf][kk][nq+1] = to_tf32(rb[j].y);
                Bs[buf][kk][nq+2] = to_tf32(rb[j].z);
                Bs[buf][kk][nq+3] = to_tf32(rb[j].w); }
            else            { int row = i >> 2, kq = (i & 3) * 4;
                Bs[buf][kq+0][row] = to_tf32(rb[j].x);
                Bs[buf][kq+1][row] = to_tf32(rb[j].y);
                Bs[buf][kq+2][row] = to_tf32(rb[j].z);
                Bs[buf][kq+3][row] = to_tf32(rb[j].w); }
        }
    };

    auto compute = [&](int buf){
        #pragma unroll
        for (int ks = 0; ks < 16; ks += 8){
            uint32_t af[2][4], bf[8][2];
            #pragma unroll
            for (int im = 0; im < 2; im++){
                af[im][0] = U(As[buf][ks+qc  ][wm+im*16+r  ]);
                af[im][1] = U(As[buf][ks+qc  ][wm+im*16+r+8]);
                af[im][2] = U(As[buf][ks+qc+4][wm+im*16+r  ]);
                af[im][3] = U(As[buf][ks+qc+4][wm+im*16+r+8]);
            }
            #pragma unroll
            for (int jn = 0; jn < 8; jn++){
                bf[jn][0] = U(Bs[buf][ks+qc  ][wn+jn*8+r]);
                bf[jn][1] = U(Bs[buf][ks+qc+4][wn+jn*8+r]);
            }
            #pragma unroll
            for (int im = 0; im < 2; im++)
                #pragma unroll
                for (int jn = 0; jn < 8; jn++)
                    mma_tf32(acc[im][jn], af[im][0], af[im][1], af[im][2], af[im][3],
                             bf[jn][0], bf[jn][1]);
        }
    };

    gload(0); sstore(0); __syncthreads();
    int buf = 0;
    for (int k0 = 0; k0 < K; k0 += 16){
        bool more = (k0 + 16) < K;
        if (more) gload(k0 + 16);
        compute(buf);
        if (more) { sstore(buf ^ 1); buf ^= 1; }
        __syncthreads();
    }

    #pragma unroll
    for (int im = 0; im < 2; im++){
        float sl = 0.f, s2l = 0.f, shv = 0.f, s2h = 0.f;
        #pragma unroll
        for (int jn = 0; jn < 8; jn++){
            float v0 = acc[im][jn][0], v1 = acc[im][jn][1];
            float v2 = acc[im][jn][2], v3 = acc[im][jn][3];
            int row = bm + wm + im*16 + r;
            int col = bn + wn + jn*8 + 2*qc;
            *reinterpret_cast<float2*>(&Cz[(long)row * N + col])     = make_float2(v0, v1);
            *reinterpret_cast<float2*>(&Cz[(long)(row+8) * N + col]) = make_float2(v2, v3);
            if (STATS) {
                sl  += v0 + v1;       s2l += v0*v0 + v1*v1;
                shv += v2 + v3;       s2h += v2*v2 + v3*v3;
            }
        }
        if (STATS) {
            sl  += __shfl_xor_sync(0xffffffffu, sl, 1);
            sl  += __shfl_xor_sync(0xffffffffu, sl, 2);
            s2l += __shfl_xor_sync(0xffffffffu, s2l, 1);
            s2l += __shfl_xor_sync(0xffffffffu, s2l, 2);
            shv += __shfl_xor_sync(0xffffffffu, shv, 1);
            shv += __shfl_xor_sync(0xffffffffu, shv, 2);
            s2h += __shfl_xor_sync(0xffffffffu, s2h, 1);
            s2h += __shfl_xor_sync(0xffffffffu, s2h, 2);
            if (qc == 0) {
                int row = bm + wm + im*16 + r;
                atomicAdd(&gS[row],    sl);
                atomicAdd(&gS2[row],   s2l);
                atomicAdd(&gS[row+8],  shv);
                atomicAdd(&gS2[row+8], s2h);
            }
        }
    }
}

// =====================================================================
// V transpose + BN, coefficients computed inline from qkv raw sums
// =====================================================================
__global__ __launch_bounds__(256) void transpose_v(const float* __restrict__ y,
    float* __restrict__ vt,
    const float* __restrict__ sQ, const float* __restrict__ sQ2,
    const float* __restrict__ gg, const float* __restrict__ bbias)
{
    __shared__ float t[32][33];
    const int z = blockIdx.z, b = z >> 3, h = z & 7;
    const float* V = y + ((long)b * QKV_C + h * 192 + 64) * Nn;
    const int n0 = blockIdx.x * 32, d0 = blockIdx.y * 32;
    const int tx = threadIdx.x, ty = threadIdx.y;  // 32 x 8
    #pragma unroll
    for (int j = 0; j < 4; j++){
        int d = d0 + ty + j*8;
        int ch = h*192 + 64 + d;
        float m = sQ[ch]*INV_BN;
        float var = sQ2[ch]*INV_BN - m*m;
        float a = rsqrtf(var + EPS)*gg[ch];
        float sh = bbias[ch] - m*a;
        t[ty + j*8][tx] = V[(long)d * Nn + n0 + tx] * a + sh;
    }
    __syncthreads();
    float* dst = vt + (long)z * Nn * VD;
    #pragma unroll
    for (int j = 0; j < 4; j++)
        dst[(long)(n0 + ty + j*8) * VD + d0 + tx] = to_tf32(t[tx][ty + j*8]);
}

// =====================================================================
// Flash attention — R11 loop body EXACTLY (measured best 206us);
// preamble computes BN coefficients inline from qkv raw sums.
// =====================================================================
#define FQ  0
#define FK  (4*8*32*4)
#define FV  (FK + 32*132)
#define FP  (FV + 64*132)
#define FCO (FP + 64*136)
#define FLS (FCO + 128)
#define FTOT ((FLS + 128) * 4)

__global__ __launch_bounds__(256,2) void flash_att(
    const float* __restrict__ y, const float* __restrict__ vt,
    float* __restrict__ o2t,
    const float* __restrict__ sQ, const float* __restrict__ sQ2,
    const float* __restrict__ gg, const float* __restrict__ bbias,
    float scale)
{
    extern __shared__ float sm[];
    float* Qp = sm + FQ;
    float* Ks = sm + FK;
    float* Vs = sm + FV;
    float* Ps = sm + FP;
    float* co = sm + FCO;
    float* Ls = sm + FLS;

    const int z = blockIdx.y, b = z >> 3, h = z & 7;
    const float* Q   = y + ((long)b * QKV_C + h * 192) * Nn;
    const float* Kg  = Q + 32 * Nn;
    const float* Vtz = vt + (long)z * Nn * VD;
    const int qt = blockIdx.x * 128;
    const int tid = threadIdx.x, w = tid >> 5, l = tid & 31;
    const int r = l >> 2, qc = l & 3;
    const int wq = w * 16;
    const int g = w >> 1, e = w & 1;
    const int qb = g * 32;

    if (tid < 64) {
        int ch = h*192 + tid;
        float m = sQ[ch]*INV_BN;
        float var = sQ2[ch]*INV_BN - m*m;
        float a = rsqrtf(var + EPS)*gg[ch];
        float sh = bbias[ch] - m*a;
        if (tid < 32) {
            co[tid]    = a*scale*1.44269504088896f;
            co[32+tid] = sh*scale*1.44269504088896f;
        } else {
            co[32+tid] = a;   // slot 64+d for d = tid-32
            co[64+tid] = sh;  // slot 96+d
        }
    }
    __syncthreads();

    for (int i = tid; i < 32*32; i += 256) {
        int d = i >> 5, c = (i & 31) * 4;
        float a = co[d], sh = co[32+d];
        float4 v = *reinterpret_cast<const float4*>(&Q[(long)d * Nn + qt + c]);
        float vv[4] = { to_tf32(v.x*a+sh), to_tf32(v.y*a+sh),
                        to_tf32(v.z*a+sh), to_tf32(v.w*a+sh) };
        int ksb = d >> 3, dd = d & 7;
        int qcc = dd & 3, jhi = dd >> 2;
        #pragma unroll
        for (int t = 0; t < 4; t++) {
            int q = c + t;
            int ww = q >> 4, qq = q & 15;
            int rr = qq & 7, jlo = qq >> 3;
            Qp[(((ksb*8 + ww)*32) + rr*4 + qcc)*4 + jhi*2 + jlo] = vv[t];
        }
    }

    float oacc[2][8][4];
    #pragma unroll
    for (int im = 0; im < 2; im++)
        #pragma unroll
        for (int j = 0; j < 8; j++)
            oacc[im][j][0] = oacc[im][j][1] = oacc[im][j][2] = oacc[im][j][3] = 0.f;
    float l0 = 0.f, l1 = 0.f;

    for (int kt = 0; kt < Nn; kt += 64) {
        #pragma unroll
        for (int j = 0; j < 2; j++) {
            int i = tid + j*256;
            int d = i >> 4, l4 = i & 15;
            int tau = ((l4 & 7) << 1) | (l4 >> 3);
            int c = tau * 4;
            float a = co[64+d], sh = co[96+d];
            float4 v = *reinterpret_cast<const float4*>(&Kg[(long)d * Nn + kt + c]);
            int base = d*132 + (c & 7)*16 + (c >> 3);
            Ks[base     ] = to_tf32(v.x*a+sh);
            Ks[base + 16] = to_tf32(v.y*a+sh);
            Ks[base + 32] = to_tf32(v.z*a+sh);
            Ks[base + 48] = to_tf32(v.w*a+sh);
        }
        #pragma unroll
        for (int j = 0; j < 8; j++) {
            int i = tid + j*256;
            int kk = i >> 5, lane = i & 31;
            int sig = ((lane & 15) << 1) | (lane >> 4);
            int c = sig * 4;
            float4 v = *reinterpret_cast<const float4*>(&Vtz[(long)(kt + kk) * VD + c]);
            int base = kk*132 + (c & 7)*16 + (c >> 3);
            Vs[base     ] = v.x;
            Vs[base + 16] = v.y;
            Vs[base + 32] = v.z;
            Vs[base + 48] = v.w;
        }
        __syncthreads();

        float sacc[8][4];
        #pragma unroll
        for (int j = 0; j < 8; j++)
            sacc[j][0] = sacc[j][1] = sacc[j][2] = sacc[j][3] = 0.f;
        #pragma unroll
        for (int ksb = 0; ksb < 4; ksb++) {
            int ks = ksb * 8;
            float4 aq = *reinterpret_cast<const float4*>(&Qp[((ksb*8 + w)*32 + l)*4]);
            uint32_t a0 = U(aq.x), a1 = U(aq.y), a2 = U(aq.z), a3 = U(aq.w);
            float4 kL0 = *reinterpret_cast<const float4*>(&Ks[(ks+qc  )*132 + r*16    ]);
            float4 kL1 = *reinterpret_cast<const float4*>(&Ks[(ks+qc  )*132 + r*16 + 4]);
            float4 kH0 = *reinterpret_cast<const float4*>(&Ks[(ks+qc+4)*132 + r*16    ]);
            float4 kH1 = *reinterpret_cast<const float4*>(&Ks[(ks+qc+4)*132 + r*16 + 4]);
            mma_tf32(sacc[0], a0,a1,a2,a3, U(kL0.x),U(kH0.x));
            mma_tf32(sacc[1], a0,a1,a2,a3, U(kL0.y),U(kH0.y));
            mma_tf32(sacc[2], a0,a1,a2,a3, U(kL0.z),U(kH0.z));
            mma_tf32(sacc[3], a0,a1,a2,a3, U(kL0.w),U(kH0.w));
            mma_tf32(sacc[4], a0,a1,a2,a3, U(kL1.x),U(kH1.x));
            mma_tf32(sacc[5], a0,a1,a2,a3, U(kL1.y),U(kH1.y));
            mma_tf32(sacc[6], a0,a1,a2,a3, U(kL1.z),U(kH1.z));
            mma_tf32(sacc[7], a0,a1,a2,a3, U(kL1.w),U(kH1.w));
        }

        float rs0 = 0.f, rs1 = 0.f;
        #pragma unroll
        for (int jn = 0; jn < 8; jn++) {
            sacc[jn][0] = ex2_approx(sacc[jn][0]);
            sacc[jn][1] = ex2_approx(sacc[jn][1]);
            sacc[jn][2] = ex2_approx(sacc[jn][2]);
            sacc[jn][3] = ex2_approx(sacc[jn][3]);
            rs0 += sacc[jn][0] + sacc[jn][1];
            rs1 += sacc[jn][2] + sacc[jn][3];
        }
        rs0 += __shfl_xor_sync(0xffffffffu, rs0, 1);
        rs0 += __shfl_xor_sync(0xffffffffu, rs0, 2);
        rs1 += __shfl_xor_sync(0xffffffffu, rs1, 1);
        rs1 += __shfl_xor_sync(0xffffffffu, rs1, 2);
        l0 += rs0;
        l1 += rs1;

        #pragma unroll
        for (int jn = 0; jn < 8; jn++) {
            int col = jn*8 + 2*qc;
            Ps[(col  )*136 + wq + r    ] = to_tf32(sacc[jn][0]);
            Ps[(col+1)*136 + wq + r    ] = to_tf32(sacc[jn][1]);
            Ps[(col  )*136 + wq + r + 8] = to_tf32(sacc[jn][2]);
            Ps[(col+1)*136 + wq + r + 8] = to_tf32(sacc[jn][3]);
        }
        __syncthreads();

        #pragma unroll
        for (int ks = 0; ks < 64; ks += 8) {
            uint32_t pa[2][4];
            #pragma unroll
            for (int im = 0; im < 2; im++) {
                int cb = qb + im*16;
                pa[im][0] = U(Ps[(ks+qc  )*136 + cb + r    ]);
                pa[im][1] = U(Ps[(ks+qc  )*136 + cb + r + 8]);
                pa[im][2] = U(Ps[(ks+qc+4)*136 + cb + r    ]);
                pa[im][3] = U(Ps[(ks+qc+4)*136 + cb + r + 8]);
            }
            #pragma unroll
            for (int q = 0; q < 2; q++) {
                int qh = 2*e + q;
                float4 vL = *reinterpret_cast<const float4*>(&Vs[(ks+qc  )*132 + r*16 + qh*4]);
                float4 vH = *reinterpret_cast<const float4*>(&Vs[(ks+qc+4)*132 + r*16 + qh*4]);
                #pragma unroll
                for (int im = 0; im < 2; im++) {
                    mma_tf32(oacc[im][q*4+0], pa[im][0],pa[im][1],pa[im][2],pa[im][3], U(vL.x),U(vH.x));
                    mma_tf32(oacc[im][q*4+1], pa[im][0],pa[im][1],pa[im][2],pa[im][3], U(vL.y),U(vH.y));
                    mma_tf32(oacc[im][q*4+2], pa[im][0],pa[im][1],pa[im][2],pa[im][3], U(vL.z),U(vH.z));
                    mma_tf32(oacc[im][q*4+3], pa[im][0],pa[im][1],pa[im][2],pa[im][3], U(vL.w),U(vH.w));
                }
            }
        }
        __syncthreads();
    }

    if (qc == 0) {
        Ls[wq + r    ] = l0;
        Ls[wq + r + 8] = l1;
    }
    __syncthreads();

    #pragma unroll
    for (int im = 0; im < 2; im++) {
        float inv0 = 1.f / Ls[qb + im*16 + r    ];
        float inv1 = 1.f / Ls[qb + im*16 + r + 8];
        #pragma unroll
        for (int jn = 0; jn < 8; jn++) {
            int ch = h * VD + e*64 + jn*8 + 2*qc;
            float v0 = gelu_exact(oacc[im][jn][0] * inv0);
            float v1 = gelu_exact(oacc[im][jn][1] * inv0);
            float v2 = gelu_exact(oacc[im][jn][2] * inv1);
            float v3 = gelu_exact(oacc[im][jn][3] * inv1);
            long base = ((long)b * Nn + qt + qb + im*16 + r) * (long)(HEADS*VD) + ch;
            *reinterpret_cast<float2*>(&o2t[base]) = make_float2(v0, v1);
            *reinterpret_cast<float2*>(&o2t[base + 8L*(HEADS*VD)]) = make_float2(v2, v3);
        }
    }
}

// ---------------- BN apply + residual, inline finalize from raw sums ------------
// ZEROQ=1: block 0 additionally re-zeroes the qkv sum buffers for replay
// (safe: qkv sums were consumed earlier in this graph; next use is next replay).
template<int ZEROQ>
__global__ __launch_bounds__(256) void bn_apply_residual_stats(
    const float* __restrict__ src, const float* __restrict__ res,
    float* __restrict__ dst, const float* __restrict__ sum, const float* __restrict__ sum2,
    const float* __restrict__ gg, const float* __restrict__ bb, int C, long total4)
{
    if (ZEROQ && blockIdx.x == 0) {
        for (int i = threadIdx.x; i < QKV_C; i += 256) { g_csQ[i] = 0.f; g_csQ2[i] = 0.f; }
    }
    const float4* s4 = reinterpret_cast<const float4*>(src);
    const float4* r4 = reinterpret_cast<const float4*>(res);
    float4* d4 = reinterpret_cast<float4*>(dst);
    long stride = (long)gridDim.x * blockDim.x;
    for (long i = (long)blockIdx.x * blockDim.x + threadIdx.x; i < total4; i += stride) {
        int c = (int)((i >> 8) % C);
        float m = sum[c] * INV_BN;
        float var = sum2[c] * INV_BN - m * m;
        float sc = rsqrtf(var + EPS) * gg[c];
        float shf = bb[c] - m * sc;
        float4 v = s4[i]; float4 rr = r4[i];
        v.x = rr.x + v.x * sc + shf; v.y = rr.y + v.y * sc + shf;
        v.z = rr.z + v.z * sc + shf; v.w = rr.w + v.w * sc + shf;
        d4[i] = v;
    }
}

// ---------------- launch ----------------
extern "C" void kernel_launch(void* const* d_in, const int* in_sizes, int n_in,
                              void* d_out, int out_size)
{
    const float* x       = (const float*)d_in[0];
    const float* w_qkv   = (const float*)d_in[1];
    const float* gqkv    = (const float*)d_in[2];
    const float* bqkv    = (const float*)d_in[3];
    const float* w_merge = (const float*)d_in[4];
    const float* gmerge  = (const float*)d_in[5];
    const float* bmerge  = (const float*)d_in[6];
    const float* w_fc1   = (const float*)d_in[7];
    const float* gfc1    = (const float*)d_in[8];
    const float* bfc1    = (const float*)d_in[9];
    const float* w_fc2   = (const float*)d_in[10];
    const float* gfc2    = (const float*)d_in[11];
    const float* bfc2    = (const float*)d_in[12];
    float* out = (float*)d_out;

    float *yb, *vtb, *o2tb, *x2b, *h1b, *tmpb;
    float *csQb, *csQ2b, *cs1b, *cs1_2b, *csMb, *csM2b, *csFb, *csF2b;
    cudaGetSymbolAddress((void**)&yb,     g_y);
    cudaGetSymbolAddress((void**)&vtb,    g_vt);
    cudaGetSymbolAddress((void**)&o2tb,   g_o2t);
    cudaGetSymbolAddress((void**)&x2b,    g_x2);
    cudaGetSymbolAddress((void**)&h1b,    g_h1);
    cudaGetSymbolAddress((void**)&tmpb,   g_tmp);
    cudaGetSymbolAddress((void**)&csQb,   g_csQ);
    cudaGetSymbolAddress((void**)&csQ2b,  g_csQ2);
    cudaGetSymbolAddress((void**)&cs1b,   g_cs1);
    cudaGetSymbolAddress((void**)&cs1_2b, g_cs1_2);
    cudaGetSymbolAddress((void**)&csMb,   g_csM);
    cudaGetSymbolAddress((void**)&csM2b,  g_csM2);
    cudaGetSymbolAddress((void**)&csFb,   g_csF);
    cudaGetSymbolAddress((void**)&csF2b,  g_csF2);

    static bool attr_done = false;
    if (!attr_done) {
        cudaFuncSetAttribute(flash_att, cudaFuncAttributeMaxDynamicSharedMemorySize, FTOT);
        attr_done = true;
    }

    const float scale = 0.17677669529663687f;

    // 1) qkv conv + fused stats -> csQ (+replay re-zero of downstream sum buffers)
    mm_tf32<0,0,0,1,1><<<dim3(Nn/128, QKV_C/128, Bb), 256>>>(
        w_qkv, x, yb, QKV_C, Nn, Cc, Cc, Nn, (long)Cc*Nn, (long)QKV_C*Nn,
        nullptr, nullptr, nullptr, nullptr, csQb, csQ2b);
    // 2) V transpose + BN (inline coeffs from csQ)
    transpose_v<<<dim3(Nn/32, VD/32, Bb*HEADS), dim3(32,8)>>>(yb, vtb, csQb, csQ2b, gqkv, bqkv);
    // 3) flash attention (inline BN coeffs) + gelu
    flash_att<<<dim3(Nn/128, Bb*HEADS), 256, FTOT>>>(yb, vtb, o2tb,
        csQb, csQ2b, gqkv, bqkv, scale);
    // 4) merge conv + fused stats -> csM; inline-finalized BN + residual -> x2
    mm_tf32<0,1,0,1,0><<<dim3(Nn/128, Cc/128, Bb), 256>>>(
        w_merge, o2tb, tmpb, Cc, Nn, HEADS*VD, HEADS*VD, HEADS*VD,
        (long)Nn*HEADS*VD, (long)Cc*Nn, nullptr, nullptr, nullptr, nullptr, csMb, csM2b);
    bn_apply_residual_stats<0><<<1024, 256>>>(tmpb, x, x2b, csMb, csM2b, gmerge, bmerge, Cc, (long)Bb*Cc*Nn/4);
    // 5) fc1 + fused stats -> cs1
    mm_tf32<0,0,0,1,0><<<dim3(Nn/128, FC1_C/128, Bb), 256>>>(
        w_fc1, x2b, tmpb, FC1_C, Nn, Cc, Cc, Nn, (long)Cc*Nn, (long)FC1_C*Nn,
        nullptr, nullptr, nullptr, nullptr, cs1b, cs1_2b);
    // 6) fc2 with fc1's BN+gelu (inline from cs1) fused into B loads + stats -> csF
    mm_tf32<0,0,1,1,0><<<dim3(Nn/128, Cc/128, Bb), 256>>>(
        w_fc2, tmpb, h1b, Cc, Nn, FC1_C, FC1_C, Nn, (long)FC1_C*Nn, (long)Cc*Nn,
        cs1b, cs1_2b, gfc1, bfc1, csFb, csF2b);
    // 7) final: inline-finalized BN + residual -> out (+re-zero qkv sums for replay)
    bn_apply_residual_stats<1><<<1024, 256>>>(h1b, x2b, out, csFb, csF2b, gfc2, bfc2, Cc, (long)Bb*Cc*Nn/4);
}

// round 15
// speedup vs baseline: 1.0435x; 1.0155x over previous
#include <cuda_runtime.h>
#include <math.h>
#include <stdint.h>

#define Bb 8
#define Cc 384
#define Nn 1024
#define HEADS 8
#define KD 32
#define VD 128
#define QKV_C 1536
#define FC1_C 768
#define EPS 1e-5f
#define INV_BN (1.0f/8192.0f)

// ---------------- scratch (static device globals; no allocation) ----------------
__device__ float g_y[(long)Bb*QKV_C*Nn];
__device__ float g_vt[(long)Bb*HEADS*Nn*VD];
__device__ float g_o2t[(long)Bb*Nn*HEADS*VD];
__device__ float g_x2[(long)Bb*Cc*Nn];
__device__ float g_h1[(long)Bb*FC1_C*Nn];
__device__ float g_tmp[(long)Bb*FC1_C*Nn];
__device__ float g_csQ[QKV_C];
__device__ float g_csQ2[QKV_C];
__device__ float g_cs1[FC1_C];
__device__ float g_cs1_2[FC1_C];
__device__ float g_csM[Cc];
__device__ float g_csM2[Cc];
__device__ float g_csF[Cc];
__device__ float g_csF2[Cc];

__device__ __forceinline__ float gelu_exact(float x){
    return 0.5f * x * (1.0f + erff(x * 0.7071067811865476f));
}
__device__ __forceinline__ float to_tf32(float x){
    uint32_t u;
    asm("cvt.rna.tf32.f32 %0, %1;" : "=r"(u) : "f"(x));
    return __uint_as_float(u);
}
__device__ __forceinline__ float ex2_approx(float x){
    float y;
    asm("ex2.approx.ftz.f32 %0, %1;" : "=f"(y) : "f"(x));
    return y;
}
__device__ __forceinline__ void mma_tf32(float c[4],
    uint32_t a0, uint32_t a1, uint32_t a2, uint32_t a3, uint32_t b0, uint32_t b1)
{
    asm volatile("mma.sync.aligned.m16n8k8.row.col.f32.tf32.tf32.f32 "
        "{%0,%1,%2,%3}, {%4,%5,%6,%7}, {%8,%9}, {%0,%1,%2,%3};"
        : "+f"(c[0]), "+f"(c[1]), "+f"(c[2]), "+f"(c[3])
        : "r"(a0), "r"(a1), "r"(a2), "r"(a3), "r"(b0), "r"(b1));
}
#define U(f) __float_as_uint(f)

// =====================================================================
// tf32 GEMM — R11/R14 body with CONFLICT-FREE tile stores:
//  element (k, x) lives at column  x ^ ((k>>2 & 3) << 3)
//  - A-store / BMODE1 B-store (transposed, scalar): per-lane swizzle
//    (i&3)<<3 -> 32 distinct banks per STS.
//  - BMODE0 B-store: single STS.128 at nq ^ sw (contiguous, CF).
//  - Fragment loads XOR the per-instruction constant ((k>>2)&3)<<3;
//    banks stay r + 8*(qc+d) -> conflict-free.
// =====================================================================
#define SMS 136

template<int BMODE,int BNB,int STATS,int ZEROST>
__global__ __launch_bounds__(256,2) void mm_tf32(
    const float* __restrict__ A, const float* __restrict__ B, float* __restrict__ C,
    int M, int N, int K, int lda, int ldb,
    long strideB, long strideC,
    const float* __restrict__ bnS, const float* __restrict__ bnS2,
    const float* __restrict__ bnG, const float* __restrict__ bnBv,
    float* __restrict__ gS, float* __restrict__ gS2)
{
    __shared__ __align__(16) float As[2][16][SMS];
    __shared__ __align__(16) float Bs[2][16][SMS];

    const int tid = threadIdx.x;
    if (ZEROST && blockIdx.x == 0 && blockIdx.y == 0 && blockIdx.z == 0) {
        for (int i = tid; i < FC1_C; i += 256) { g_cs1[i] = 0.f; g_cs1_2[i] = 0.f; }
        for (int i = tid; i < Cc; i += 256) {
            g_csM[i] = 0.f; g_csM2[i] = 0.f;
            g_csF[i] = 0.f; g_csF2[i] = 0.f;
        }
    }

    const int z = blockIdx.z;
    const float* Ab = A;
    const float* Bc = B + (long)z * strideB;
    float* Cz = C + (long)z * strideC;

    const int bm = blockIdx.y * 128, bn = blockIdx.x * 128;
    const int w = tid >> 5, l = tid & 31;
    const int wm = (w >> 1) * 32, wn = (w & 1) * 64;
    const int r = l >> 2, qc = l & 3;

    float acc[2][8][4];
    #pragma unroll
    for (int i = 0; i < 2; i++)
        #pragma unroll
        for (int j = 0; j < 8; j++)
            #pragma unroll
            for (int k = 0; k < 4; k++) acc[i][j][k] = 0.f;

    float4 ra[2], rb[2];

    auto gload = [&](int k0){
        #pragma unroll
        for (int j = 0; j < 2; j++){
            int i = tid + j*256;
            int row = i >> 2, kq = (i & 3) * 4;
            ra[j] = *reinterpret_cast<const float4*>(&Ab[(long)(bm+row)*lda + k0+kq]);
        }
        #pragma unroll
        for (int j = 0; j < 2; j++){
            int i = tid + j*256;
            if (BMODE == 0) { int kk = i >> 5, nq = (i & 31) * 4;
                rb[j] = *reinterpret_cast<const float4*>(&Bc[(long)(k0+kk)*ldb + bn+nq]);
                if (BNB) {
                    int c = k0 + kk;
                    float m = bnS[c]*INV_BN;
                    float var = bnS2[c]*INV_BN - m*m;
                    float a = rsqrtf(var + EPS)*bnG[c];
                    float sh = bnBv[c] - m*a;
                    rb[j].x = gelu_exact(rb[j].x*a+sh);
                    rb[j].y = gelu_exact(rb[j].y*a+sh);
                    rb[j].z = gelu_exact(rb[j].z*a+sh);
                    rb[j].w = gelu_exact(rb[j].w*a+sh);
                } }
            else            { int row = i >> 2, kq = (i & 3) * 4;
                rb[j] = *reinterpret_cast<const float4*>(&Bc[(long)(bn+row)*ldb + k0+kq]); }
        }
    };

    auto sstore = [&](int buf){
        #pragma unroll
        for (int j = 0; j < 2; j++){
            int i = tid + j*256;
            int row = i >> 2, kq = (i & 3) * 4;
            int col = row ^ ((i & 3) << 3);
            As[buf][kq+0][col] = to_tf32(ra[j].x);
            As[buf][kq+1][col] = to_tf32(ra[j].y);
            As[buf][kq+2][col] = to_tf32(ra[j].z);
            As[buf][kq+3][col] = to_tf32(ra[j].w);
        }
        #pragma unroll
        for (int j = 0; j < 2; j++){
            int i = tid + j*256;
            if (BMODE == 0) { int kk = i >> 5, nq = (i & 31) * 4;
                int col = nq ^ (((kk >> 2) & 3) << 3);
                float4 t4 = make_float4(to_tf32(rb[j].x), to_tf32(rb[j].y),
                                        to_tf32(rb[j].z), to_tf32(rb[j].w));
                *reinterpret_cast<float4*>(&Bs[buf][kk][col]) = t4; }
            else            { int row = i >> 2, kq = (i & 3) * 4;
                int col = row ^ ((i & 3) << 3);
                Bs[buf][kq+0][col] = to_tf32(rb[j].x);
                Bs[buf][kq+1][col] = to_tf32(rb[j].y);
                Bs[buf][kq+2][col] = to_tf32(rb[j].z);
                Bs[buf][kq+3][col] = to_tf32(rb[j].w); }
        }
    };

    auto compute = [&](int buf){
        #pragma unroll
        for (int ks = 0; ks < 16; ks += 8){
            const int c0 = ((ks >> 2) & 3) << 3;       // swizzle for k in [ks, ks+4)
            const int c1 = (((ks+4) >> 2) & 3) << 3;   // swizzle for k in [ks+4, ks+8)
            uint32_t af[2][4], bf[8][2];
            #pragma unroll
            for (int im = 0; im < 2; im++){
                af[im][0] = U(As[buf][ks+qc  ][(wm+im*16+r  ) ^ c0]);
                af[im][1] = U(As[buf][ks+qc  ][(wm+im*16+r+8) ^ c0]);
                af[im][2] = U(As[buf][ks+qc+4][(wm+im*16+r  ) ^ c1]);
                af[im][3] = U(As[buf][ks+qc+4][(wm+im*16+r+8) ^ c1]);
            }
            #pragma unroll
            for (int jn = 0; jn < 8; jn++){
                bf[jn][0] = U(Bs[buf][ks+qc  ][(wn+jn*8+r) ^ c0]);
                bf[jn][1] = U(Bs[buf][ks+qc+4][(wn+jn*8+r) ^ c1]);
            }
            #pragma unroll
            for (int im = 0; im < 2; im++)
                #pragma unroll
                for (int jn = 0; jn < 8; jn++)
                    mma_tf32(acc[im][jn], af[im][0], af[im][1], af[im][2], af[im][3],
                             bf[jn][0], bf[jn][1]);
        }
    };

    gload(0); sstore(0); __syncthreads();
    int buf = 0;
    for (int k0 = 0; k0 < K; k0 += 16){
        bool more = (k0 + 16) < K;
        if (more) gload(k0 + 16);
        compute(buf);
        if (more) { sstore(buf ^ 1); buf ^= 1; }
        __syncthreads();
    }

    #pragma unroll
    for (int im = 0; im < 2; im++){
        float sl = 0.f, s2l = 0.f, shv = 0.f, s2h = 0.f;
        #pragma unroll
        for (int jn = 0; jn < 8; jn++){
            float v0 = acc[im][jn][0], v1 = acc[im][jn][1];
            float v2 = acc[im][jn][2], v3 = acc[im][jn][3];
            int row = bm + wm + im*16 + r;
            int col = bn + wn + jn*8 + 2*qc;
            *reinterpret_cast<float2*>(&Cz[(long)row * N + col])     = make_float2(v0, v1);
            *reinterpret_cast<float2*>(&Cz[(long)(row+8) * N + col]) = make_float2(v2, v3);
            if (STATS) {
                sl  += v0 + v1;       s2l += v0*v0 + v1*v1;
                shv += v2 + v3;       s2h += v2*v2 + v3*v3;
            }
        }
        if (STATS) {
            sl  += __shfl_xor_sync(0xffffffffu, sl, 1);
            sl  += __shfl_xor_sync(0xffffffffu, sl, 2);
            s2l += __shfl_xor_sync(0xffffffffu, s2l, 1);
            s2l += __shfl_xor_sync(0xffffffffu, s2l, 2);
            shv += __shfl_xor_sync(0xffffffffu, shv, 1);
            shv += __shfl_xor_sync(0xffffffffu, shv, 2);
            s2h += __shfl_xor_sync(0xffffffffu, s2h, 1);
            s2h += __shfl_xor_sync(0xffffffffu, s2h, 2);
            if (qc == 0) {
                int row = bm + wm + im*16 + r;
                atomicAdd(&gS[row],    sl);
                atomicAdd(&gS2[row],   s2l);
                atomicAdd(&gS[row+8],  shv);
                atomicAdd(&gS2[row+8], s2h);
            }
        }
    }
}

// =====================================================================
// V transpose + BN, coefficients inline from qkv raw sums
// =====================================================================
__global__ __launch_bounds__(256) void transpose_v(const float* __restrict__ y,
    float* __restrict__ vt,
    const float* __restrict__ sQ, const float* __restrict__ sQ2,
    const float* __restrict__ gg, const float* __restrict__ bbias)
{
    __shared__ float t[32][33];
    const int z = blockIdx.z, b = z >> 3, h = z & 7;
    const float* V = y + ((long)b * QKV_C + h * 192 + 64) * Nn;
    const int n0 = blockIdx.x * 32, d0 = blockIdx.y * 32;
    const int tx = threadIdx.x, ty = threadIdx.y;
    #pragma unroll
    for (int j = 0; j < 4; j++){
        int d = d0 + ty + j*8;
        int ch = h*192 + 64 + d;
        float m = sQ[ch]*INV_BN;
        float var = sQ2[ch]*INV_BN - m*m;
        float a = rsqrtf(var + EPS)*gg[ch];
        float sh = bbias[ch] - m*a;
        t[ty + j*8][tx] = V[(long)d * Nn + n0 + tx] * a + sh;
    }
    __syncthreads();
    float* dst = vt + (long)z * Nn * VD;
    #pragma unroll
    for (int j = 0; j < 4; j++)
        dst[(long)(n0 + ty + j*8) * VD + d0 + tx] = to_tf32(t[tx][ty + j*8]);
}

// =====================================================================
// Flash attention — R11 loop body EXACTLY; preamble inline BN coeffs.
// =====================================================================
#define FQ  0
#define FK  (4*8*32*4)
#define FV  (FK + 32*132)
#define FP  (FV + 64*132)
#define FCO (FP + 64*136)
#define FLS (FCO + 128)
#define FTOT ((FLS + 128) * 4)

__global__ __launch_bounds__(256,2) void flash_att(
    const float* __restrict__ y, const float* __restrict__ vt,
    float* __restrict__ o2t,
    const float* __restrict__ sQ, const float* __restrict__ sQ2,
    const float* __restrict__ gg, const float* __restrict__ bbias,
    float scale)
{
    extern __shared__ float sm[];
    float* Qp = sm + FQ;
    float* Ks = sm + FK;
    float* Vs = sm + FV;
    float* Ps = sm + FP;
    float* co = sm + FCO;
    float* Ls = sm + FLS;

    const int z = blockIdx.y, b = z >> 3, h = z & 7;
    const float* Q   = y + ((long)b * QKV_C + h * 192) * Nn;
    const float* Kg  = Q + 32 * Nn;
    const float* Vtz = vt + (long)z * Nn * VD;
    const int qt = blockIdx.x * 128;
    const int tid = threadIdx.x, w = tid >> 5, l = tid & 31;
    const int r = l >> 2, qc = l & 3;
    const int wq = w * 16;
    const int g = w >> 1, e = w & 1;
    const int qb = g * 32;

    if (tid < 64) {
        int ch = h*192 + tid;
        float m = sQ[ch]*INV_BN;
        float var = sQ2[ch]*INV_BN - m*m;
        float a = rsqrtf(var + EPS)*gg[ch];
        float sh = bbias[ch] - m*a;
        if (tid < 32) {
            co[tid]    = a*scale*1.44269504088896f;
            co[32+tid] = sh*scale*1.44269504088896f;
        } else {
            co[32+tid] = a;
            co[64+tid] = sh;
        }
    }
    __syncthreads();

    for (int i = tid; i < 32*32; i += 256) {
        int d = i >> 5, c = (i & 31) * 4;
        float a = co[d], sh = co[32+d];
        float4 v = *reinterpret_cast<const float4*>(&Q[(long)d * Nn + qt + c]);
        float vv[4] = { to_tf32(v.x*a+sh), to_tf32(v.y*a+sh),
                        to_tf32(v.z*a+sh), to_tf32(v.w*a+sh) };
        int ksb = d >> 3, dd = d & 7;
        int qcc = dd & 3, jhi = dd >> 2;
        #pragma unroll
        for (int t = 0; t < 4; t++) {
            int q = c + t;
            int ww = q >> 4, qq = q & 15;
            int rr = qq & 7, jlo = qq >> 3;
            Qp[(((ksb*8 + ww)*32) + rr*4 + qcc)*4 + jhi*2 + jlo] = vv[t];
        }
    }

    float oacc[2][8][4];
    #pragma unroll
    for (int im = 0; im < 2; im++)
        #pragma unroll
        for (int j = 0; j < 8; j++)
            oacc[im][j][0] = oacc[im][j][1] = oacc[im][j][2] = oacc[im][j][3] = 0.f;
    float l0 = 0.f, l1 = 0.f;

    for (int kt = 0; kt < Nn; kt += 64) {
        #pragma unroll
        for (int j = 0; j < 2; j++) {
            int i = tid + j*256;
            int d = i >> 4, l4 = i & 15;
            int tau = ((l4 & 7) << 1) | (l4 >> 3);
            int c = tau * 4;
            float a = co[64+d], sh = co[96+d];
            float4 v = *reinterpret_cast<const float4*>(&Kg[(long)d * Nn + kt + c]);
            int base = d*132 + (c & 7)*16 + (c >> 3);
            Ks[base     ] = to_tf32(v.x*a+sh);
            Ks[base + 16] = to_tf32(v.y*a+sh);
            Ks[base + 32] = to_tf32(v.z*a+sh);
            Ks[base + 48] = to_tf32(v.w*a+sh);
        }
        #pragma unroll
        for (int j = 0; j < 8; j++) {
            int i = tid + j*256;
            int kk = i >> 5, lane = i & 31;
            int sig = ((lane & 15) << 1) | (lane >> 4);
            int c = sig * 4;
            float4 v = *reinterpret_cast<const float4*>(&Vtz[(long)(kt + kk) * VD + c]);
            int base = kk*132 + (c & 7)*16 + (c >> 3);
            Vs[base     ] = v.x;
            Vs[base + 16] = v.y;
            Vs[base + 32] = v.z;
            Vs[base + 48] = v.w;
        }
        __syncthreads();

        float sacc[8][4];
        #pragma unroll
        for (int j = 0; j < 8; j++)
            sacc[j][0] = sacc[j][1] = sacc[j][2] = sacc[j][3] = 0.f;
        #pragma unroll
        for (int ksb = 0; ksb < 4; ksb++) {
            int ks = ksb * 8;
            float4 aq = *reinterpret_cast<const float4*>(&Qp[((ksb*8 + w)*32 + l)*4]);
            uint32_t a0 = U(aq.x), a1 = U(aq.y), a2 = U(aq.z), a3 = U(aq.w);
            float4 kL0 = *reinterpret_cast<const float4*>(&Ks[(ks+qc  )*132 + r*16    ]);
            float4 kL1 = *reinterpret_cast<const float4*>(&Ks[(ks+qc  )*132 + r*16 + 4]);
            float4 kH0 = *reinterpret_cast<const float4*>(&Ks[(ks+qc+4)*132 + r*16    ]);
            float4 kH1 = *reinterpret_cast<const float4*>(&Ks[(ks+qc+4)*132 + r*16 + 4]);
            mma_tf32(sacc[0], a0,a1,a2,a3, U(kL0.x),U(kH0.x));
            mma_tf32(sacc[1], a0,a1,a2,a3, U(kL0.y),U(kH0.y));
            mma_tf32(sacc[2], a0,a1,a2,a3, U(kL0.z),U(kH0.z));
            mma_tf32(sacc[3], a0,a1,a2,a3, U(kL0.w),U(kH0.w));
            mma_tf32(sacc[4], a0,a1,a2,a3, U(kL1.x),U(kH1.x));
            mma_tf32(sacc[5], a0,a1,a2,a3, U(kL1.y),U(kH1.y));
            mma_tf32(sacc[6], a0,a1,a2,a3, U(kL1.z),U(kH1.z));
            mma_tf32(sacc[7], a0,a1,a2,a3, U(kL1.w),U(kH1.w));
        }

        float rs0 = 0.f, rs1 = 0.f;
        #pragma unroll
        for (int jn = 0; jn < 8; jn++) {
            sacc[jn][0] = ex2_approx(sacc[jn][0]);
            sacc[jn][1] = ex2_approx(sacc[jn][1]);
            sacc[jn][2] = ex2_approx(sacc[jn][2]);
            sacc[jn][3] = ex2_approx(sacc[jn][3]);
            rs0 += sacc[jn][0] + sacc[jn][1];
            rs1 += sacc[jn][2] + sacc[jn][3];
        }
        rs0 += __shfl_xor_sync(0xffffffffu, rs0, 1);
        rs0 += __shfl_xor_sync(0xffffffffu, rs0, 2);
        rs1 += __shfl_xor_sync(0xffffffffu, rs1, 1);
        rs1 += __shfl_xor_sync(0xffffffffu, rs1, 2);
        l0 += rs0;
        l1 += rs1;

        #pragma unroll
        for (int jn = 0; jn < 8; jn++) {
            int col = jn*8 + 2*qc;
            Ps[(col  )*136 + wq + r    ] = to_tf32(sacc[jn][0]);
            Ps[(col+1)*136 + wq + r    ] = to_tf32(sacc[jn][1]);
            Ps[(col  )*136 + wq + r + 8] = to_tf32(sacc[jn][2]);
            Ps[(col+1)*136 + wq + r + 8] = to_tf32(sacc[jn][3]);
        }
        __syncthreads();

        #pragma unroll
        for (int ks = 0; ks < 64; ks += 8) {
            uint32_t pa[2][4];
            #pragma unroll
            for (int im = 0; im < 2; im++) {
                int cb = qb + im*16;
                pa[im][0] = U(Ps[(ks+qc  )*136 + cb + r    ]);
                pa[im][1] = U(Ps[(ks+qc  )*136 + cb + r + 8]);
                pa[im][2] = U(Ps[(ks+qc+4)*136 + cb + r    ]);
                pa[im][3] = U(Ps[(ks+qc+4)*136 + cb + r + 8]);
            }
            #pragma unroll
            for (int q = 0; q < 2; q++) {
                int qh = 2*e + q;
                float4 vL = *reinterpret_cast<const float4*>(&Vs[(ks+qc  )*132 + r*16 + qh*4]);
                float4 vH = *reinterpret_cast<const float4*>(&Vs[(ks+qc+4)*132 + r*16 + qh*4]);
                #pragma unroll
                for (int im = 0; im < 2; im++) {
                    mma_tf32(oacc[im][q*4+0], pa[im][0],pa[im][1],pa[im][2],pa[im][3], U(vL.x),U(vH.x));
                    mma_tf32(oacc[im][q*4+1], pa[im][0],pa[im][1],pa[im][2],pa[im][3], U(vL.y),U(vH.y));
                    mma_tf32(oacc[im][q*4+2], pa[im][0],pa[im][1],pa[im][2],pa[im][3], U(vL.z),U(vH.z));
                    mma_tf32(oacc[im][q*4+3], pa[im][0],pa[im][1],pa[im][2],pa[im][3], U(vL.w),U(vH.w));
                }
            }
        }
        __syncthreads();
    }

    if (qc == 0) {
        Ls[wq + r    ] = l0;
        Ls[wq + r + 8] = l1;
    }
    __syncthreads();

    #pragma unroll
    for (int im = 0; im < 2; im++) {
        float inv0 = 1.f / Ls[qb + im*16 + r    ];
        float inv1 = 1.f / Ls[qb + im*16 + r + 8];
        #pragma unroll
        for (int jn = 0; jn < 8; jn++) {
            int ch = h * VD + e*64 + jn*8 + 2*qc;
            float v0 = gelu_exact(oacc[im][jn][0] * inv0);
            float v1 = gelu_exact(oacc[im][jn][1] * inv0);
            float v2 = gelu_exact(oacc[im][jn][2] * inv1);
            float v3 = gelu_exact(oacc[im][jn][3] * inv1);
            long base = ((long)b * Nn + qt + qb + im*16 + r) * (long)(HEADS*VD) + ch;
            *reinterpret_cast<float2*>(&o2t[base]) = make_float2(v0, v1);
            *reinterpret_cast<float2*>(&o2t[base + 8L*(HEADS*VD)]) = make_float2(v2, v3);
        }
    }
}

// ---------------- BN apply + residual, inline finalize from raw sums ------------
template<int ZEROQ>
__global__ __launch_bounds__(256) void bn_apply_residual_stats(
    const float* __restrict__ src, const float* __restrict__ res,
    float* __restrict__ dst, const float* __restrict__ sum, const float* __restrict__ sum2,
    const float* __restrict__ gg, const float* __restrict__ bb, int C, long total4)
{
    if (ZEROQ && blockIdx.x == 0) {
        for (int i = threadIdx.x; i < QKV_C; i += 256) { g_csQ[i] = 0.f; g_csQ2[i] = 0.f; }
    }
    const float4* s4 = reinterpret_cast<const float4*>(src);
    const float4* r4 = reinterpret_cast<const float4*>(res);
    float4* d4 = reinterpret_cast<float4*>(dst);
    long stride = (long)gridDim.x * blockDim.x;
    for (long i = (long)blockIdx.x * blockDim.x + threadIdx.x; i < total4; i += stride) {
        int c = (int)((i >> 8) % C);
        float m = sum[c] * INV_BN;
        float var = sum2[c] * INV_BN - m * m;
        float sc = rsqrtf(var + EPS) * gg[c];
        float shf = bb[c] - m * sc;
        float4 v = s4[i]; float4 rr = r4[i];
        v.x = rr.x + v.x * sc + shf; v.y = rr.y + v.y * sc + shf;
        v.z = rr.z + v.z * sc + shf; v.w = rr.w + v.w * sc + shf;
        d4[i] = v;
    }
}

// ---------------- launch ----------------
extern "C" void kernel_launch(void* const* d_in, const int* in_sizes, int n_in,
                              void* d_out, int out_size)
{
    const float* x       = (const float*)d_in[0];
    const float* w_qkv   = (const float*)d_in[1];
    const float* gqkv    = (const float*)d_in[2];
    const float* bqkv    = (const float*)d_in[3];
    const float* w_merge = (const float*)d_in[4];
    const float* gmerge  = (const float*)d_in[5];
    const float* bmerge  = (const float*)d_in[6];
    const float* w_fc1   = (const float*)d_in[7];
    const float* gfc1    = (const float*)d_in[8];
    const float* bfc1    = (const float*)d_in[9];
    const float* w_fc2   = (const float*)d_in[10];
    const float* gfc2    = (const float*)d_in[11];
    const float* bfc2    = (const float*)d_in[12];
    float* out = (float*)d_out;

    float *yb, *vtb, *o2tb, *x2b, *h1b, *tmpb;
    float *csQb, *csQ2b, *cs1b, *cs1_2b, *csMb, *csM2b, *csFb, *csF2b;
    cudaGetSymbolAddress((void**)&yb,     g_y);
    cudaGetSymbolAddress((void**)&vtb,    g_vt);
    cudaGetSymbolAddress((void**)&o2tb,   g_o2t);
    cudaGetSymbolAddress((void**)&x2b,    g_x2);
    cudaGetSymbolAddress((void**)&h1b,    g_h1);
    cudaGetSymbolAddress((void**)&tmpb,   g_tmp);
    cudaGetSymbolAddress((void**)&csQb,   g_csQ);
    cudaGetSymbolAddress((void**)&csQ2b,  g_csQ2);
    cudaGetSymbolAddress((void**)&cs1b,   g_cs1);
    cudaGetSymbolAddress((void**)&cs1_2b, g_cs1_2);
    cudaGetSymbolAddress((void**)&csMb,   g_csM);
    cudaGetSymbolAddress((void**)&csM2b,  g_csM2);
    cudaGetSymbolAddress((void**)&csFb,   g_csF);
    cudaGetSymbolAddress((void**)&csF2b,  g_csF2);

    static bool attr_done = false;
    if (!attr_done) {
        cudaFuncSetAttribute(flash_att, cudaFuncAttributeMaxDynamicSharedMemorySize, FTOT);
        attr_done = true;
    }

    const float scale = 0.17677669529663687f;

    // 1) qkv conv + fused stats -> csQ (+replay re-zero of downstream sum buffers)
    mm_tf32<0,0,1,1><<<dim3(Nn/128, QKV_C/128, Bb), 256>>>(
        w_qkv, x, yb, QKV_C, Nn, Cc, Cc, Nn, (long)Cc*Nn, (long)QKV_C*Nn,
        nullptr, nullptr, nullptr, nullptr, csQb, csQ2b);
    // 2) V transpose + BN (inline coeffs from csQ)
    transpose_v<<<dim3(Nn/32, VD/32, Bb*HEADS), dim3(32,8)>>>(yb, vtb, csQb, csQ2b, gqkv, bqkv);
    // 3) flash attention (inline BN coeffs) + gelu
    flash_att<<<dim3(Nn/128, Bb*HEADS), 256, FTOT>>>(yb, vtb, o2tb,
        csQb, csQ2b, gqkv, bqkv, scale);
    // 4) merge conv + fused stats -> csM; inline-finalized BN + residual -> x2
    mm_tf32<1,0,1,0><<<dim3(Nn/128, Cc/128, Bb), 256>>>(
        w_merge, o2tb, tmpb, Cc, Nn, HEADS*VD, HEADS*VD, HEADS*VD,
        (long)Nn*HEADS*VD, (long)Cc*Nn, nullptr, nullptr, nullptr, nullptr, csMb, csM2b);
    bn_apply_residual_stats<0><<<1024, 256>>>(tmpb, x, x2b, csMb, csM2b, gmerge, bmerge, Cc, (long)Bb*Cc*Nn/4);
    // 5) fc1 + fused stats -> cs1
    mm_tf32<0,0,1,0><<<dim3(Nn/128, FC1_C/128, Bb), 256>>>(
        w_fc1, x2b, tmpb, FC1_C, Nn, Cc, Cc, Nn, (long)Cc*Nn, (long)FC1_C*Nn,
        nullptr, nullptr, nullptr, nullptr, cs1b, cs1_2b);
    // 6) fc2 with fc1's BN+gelu (inline from cs1) fused into B loads + stats -> csF
    mm_tf32<0,1,1,0><<<dim3(Nn/128, Cc/128, Bb), 256>>>(
        w_fc2, tmpb, h1b, Cc, Nn, FC1_C, FC1_C, Nn, (long)FC1_C*Nn, (long)Cc*Nn,
        cs1b, cs1_2b, gfc1, bfc1, csFb, csF2b);
    // 7) final: inline-finalized BN + residual -> out (+re-zero qkv sums for replay)
    bn_apply_residual_stats<1><<<1024, 256>>>(h1b, x2b, out, csFb, csF2b, gfc2, bfc2, Cc, (long)Bb*Cc*Nn/4);
}